// round 1
// baseline (speedup 1.0000x reference)
#include <cuda_runtime.h>
#include <math.h>
#include <stdint.h>

#define B_   2
#define S_   1024
#define HID_ 2048
#define NH_  16
#define NKV_ 2
#define HD_  128
#define G_   (NH_/NKV_)
#define TOK  (B_*S_)

// ---------------- scratch (single __device__ array, no allocations) ----------------
// layout (floats):
//  gq   : TOK * 2048          = 4194304   off 0
//  gk   : TOK * 256           = 524288    off 4194304
//  gv   : TOK * 256           = 524288    off 4718592
//  QT   : B*NH*S*HD           = 4194304   off 5242880
//  KT   : B*NKV*S*HD          = 524288    off 9437184
//  VT   : B*NKV*S*HD          = 524288    off 9961472
//  AO   : TOK * 2048          = 4194304   off 10485760
//  eff  : 2                               off 14680064
#define OFF_GQ  0
#define OFF_GK  4194304
#define OFF_GV  4718592
#define OFF_QT  5242880
#define OFF_KT  9437184
#define OFF_VT  9961472
#define OFF_AO  10485760
#define OFF_EFF 14680064
__device__ float g_scratch[14680066];

// ---------------- eff[b] = sum_s mask[b][s] ----------------
__global__ void eff_kernel(const float* __restrict__ mask, float* __restrict__ eff) {
    int b = blockIdx.x;
    float s = 0.f;
    for (int i = threadIdx.x; i < S_; i += blockDim.x) s += mask[b * S_ + i];
    #pragma unroll
    for (int off = 16; off; off >>= 1) s += __shfl_xor_sync(0xffffffffu, s, off);
    __shared__ float red[8];
    if ((threadIdx.x & 31) == 0) red[threadIdx.x >> 5] = s;
    __syncthreads();
    if (threadIdx.x == 0) {
        float t = 0.f;
        for (int i = 0; i < (int)(blockDim.x >> 5); i++) t += red[i];
        eff[b] = t;
    }
}

// ---------------- classic fp32 SGEMM: C[M,N] = A[M,K] @ B[K,N] (+bias) ----------------
// BM=BN=128, BK=16, 256 threads, 8x8 microtile.
__global__ void __launch_bounds__(256) sgemm_bias_kernel(
    const float* __restrict__ A, const float* __restrict__ Bm,
    const float* __restrict__ bias, float* __restrict__ C,
    int M, int N, int K)
{
    const int BM = 128, BN = 128, BK = 16;
    __shared__ float As[BK][BM];   // transposed A tile
    __shared__ float Bs[BK][BN];

    int bx = blockIdx.x, by = blockIdx.y;
    int tid = threadIdx.x;
    int tr = tid / 16;   // 0..15 row group
    int tc = tid % 16;   // 0..15 col group

    float acc[8][8];
    #pragma unroll
    for (int i = 0; i < 8; i++)
        #pragma unroll
        for (int j = 0; j < 8; j++) acc[i][j] = 0.f;

    const float* Ablk = A + (size_t)by * BM * K;
    const float* Bblk = Bm + (size_t)bx * BN;

    int a_row = tid >> 2;        // 0..63
    int a_c4  = tid & 3;         // 0..3 (float4 within the 16 k-cols)
    int b_row = tid >> 5;        // 0..7
    int b_c4  = tid & 31;        // 0..31 (float4 within 128 n-cols)

    for (int k0 = 0; k0 < K; k0 += BK) {
        #pragma unroll
        for (int i = 0; i < 2; i++) {
            int r = a_row + i * 64;
            float4 v = *(const float4*)(Ablk + (size_t)r * K + k0 + a_c4 * 4);
            As[a_c4 * 4 + 0][r] = v.x;
            As[a_c4 * 4 + 1][r] = v.y;
            As[a_c4 * 4 + 2][r] = v.z;
            As[a_c4 * 4 + 3][r] = v.w;
        }
        #pragma unroll
        for (int i = 0; i < 2; i++) {
            int r = b_row + i * 8;
            *(float4*)(&Bs[r][b_c4 * 4]) =
                *(const float4*)(Bblk + (size_t)(k0 + r) * N + b_c4 * 4);
        }
        __syncthreads();

        #pragma unroll
        for (int kk = 0; kk < BK; kk++) {
            float a[8], b[8];
            *(float4*)(a)     = *(float4*)(&As[kk][tr * 8]);
            *(float4*)(a + 4) = *(float4*)(&As[kk][tr * 8 + 4]);
            *(float4*)(b)     = *(float4*)(&Bs[kk][tc * 8]);
            *(float4*)(b + 4) = *(float4*)(&Bs[kk][tc * 8 + 4]);
            #pragma unroll
            for (int i = 0; i < 8; i++)
                #pragma unroll
                for (int j = 0; j < 8; j++)
                    acc[i][j] += a[i] * b[j];
        }
        __syncthreads();
    }

    #pragma unroll
    for (int i = 0; i < 8; i++) {
        int r = by * BM + tr * 8 + i;
        #pragma unroll
        for (int j = 0; j < 8; j += 4) {
            int c = bx * BN + tc * 8 + j;
            float4 v;
            v.x = acc[i][j + 0] + (bias ? bias[c + 0] : 0.f);
            v.y = acc[i][j + 1] + (bias ? bias[c + 1] : 0.f);
            v.z = acc[i][j + 2] + (bias ? bias[c + 2] : 0.f);
            v.w = acc[i][j + 3] + (bias ? bias[c + 3] : 0.f);
            *(float4*)(C + (size_t)r * N + c) = v;
        }
    }
}

// ---------------- RMSNorm + sectioned RoPE + mask, write head-major Q/K/V ----------------
// grid: (20 units, 2048 tokens), 128 threads. units: 0..15 Q head, 16..17 K head, 18..19 V head.
__global__ void post_kernel(
    const float* __restrict__ gq, const float* __restrict__ gk, const float* __restrict__ gv,
    const float* __restrict__ cosb, const float* __restrict__ sinb,
    const float* __restrict__ mask,
    const float* __restrict__ q_gamma, const float* __restrict__ k_gamma,
    float* __restrict__ Qo, float* __restrict__ Ko, float* __restrict__ Vo)
{
    int unit = blockIdx.x;
    int t = blockIdx.y;
    int b = t >> 10, s = t & (S_ - 1);
    int d = threadIdx.x;
    float mval = mask[t];

    if (unit >= 18) {   // V: mask only
        int kh = unit - 18;
        float v = gv[(size_t)t * (NKV_ * HD_) + kh * HD_ + d];
        Vo[(((size_t)(b * NKV_ + kh)) * S_ + s) * HD_ + d] = v * mval;
        return;
    }

    float val;
    const float* gamma;
    if (unit < 16) { val = gq[(size_t)t * (NH_ * HD_) + unit * HD_ + d]; gamma = q_gamma; }
    else           { val = gk[(size_t)t * (NKV_ * HD_) + (unit - 16) * HD_ + d]; gamma = k_gamma; }

    // RMS norm over 128
    float v2 = val * val;
    #pragma unroll
    for (int off = 16; off; off >>= 1) v2 += __shfl_xor_sync(0xffffffffu, v2, off);
    __shared__ float red[4];
    __shared__ float sh[128];
    if ((d & 31) == 0) red[d >> 5] = v2;
    __syncthreads();
    float tot = red[0] + red[1] + red[2] + red[3];
    float nv = gamma[d] * val * rsqrtf(tot * (1.0f / HD_) + 1e-6f);
    sh[d] = nv;
    __syncthreads();
    float partner = (d < 64) ? -sh[d + 64] : sh[d - 64];

    // sectioned reorder: table index per d
    int sec = (d < 16) ? 0 : (d < 40) ? 1 : (d < 64) ? 2 : (d < 80) ? 0 : (d < 104) ? 1 : 2;
    size_t ci = (((size_t)sec * B_ + b) * S_ + s) * HD_ + d;
    float o = nv * cosb[ci] + partner * sinb[ci];

    if (unit < 16) {
        Qo[(((size_t)(b * NH_ + unit)) * S_ + s) * HD_ + d] = o;
    } else {
        Ko[(((size_t)(b * NKV_ + (unit - 16))) * S_ + s) * HD_ + d] = o * mval;
    }
}

// ---------------- fp32 flash attention, causal, GQA ----------------
// grid: (16 q-tiles, 16 heads, 2 batch), 256 threads (8 warps).
// BM=64 (warp owns 8 rows), BN=64 (lane owns cols l, l+32; O d-cols l+32j).
#define ATTN_SMEM ((64*128 + 64*129 + 64*128 + 64*64) * 4)
__global__ void __launch_bounds__(256, 1) attn_kernel(
    const float* __restrict__ Q, const float* __restrict__ K, const float* __restrict__ V,
    const float* __restrict__ eff, float* __restrict__ AO)
{
    extern __shared__ float sm[];
    float* Qs = sm;                  // 64*128
    float* Ks = Qs + 64 * 128;       // 64*129 (padded)
    float* Vs = Ks + 64 * 129;       // 64*128
    float* Ps = Vs + 64 * 128;       // 64*64

    int qt = blockIdx.x;
    int h  = blockIdx.y;
    int b  = blockIdx.z;
    int kvh = h / G_;

    int tid = threadIdx.x;
    int w = tid >> 5;
    int l = tid & 31;

    const float* Qg = Q + (((size_t)(b * NH_ + h) * S_) + qt * 64) * HD_;
    const float* Kg = K + ((size_t)(b * NKV_ + kvh) * S_) * HD_;
    const float* Vg = V + ((size_t)(b * NKV_ + kvh) * S_) * HD_;

    // load Q tile
    for (int i = tid; i < 64 * 32; i += 256)
        ((float4*)Qs)[i] = ((const float4*)Qg)[i];

    float m[8], lsum[8], o[8][4];
    #pragma unroll
    for (int r = 0; r < 8; r++) {
        m[r] = -1e30f; lsum[r] = 0.f;
        o[r][0] = o[r][1] = o[r][2] = o[r][3] = 0.f;
    }

    int eff_i = (int)(eff[b] + 0.5f);
    const float scale = 0.08838834764831845f;   // 128^-0.5

    for (int kt = 0; kt <= qt; kt++) {
        __syncthreads();   // previous-tile consumers done (also covers Q load on first iter)
        const float* kp = Kg + (size_t)kt * 64 * HD_;
        const float* vp = Vg + (size_t)kt * 64 * HD_;
        for (int i = tid; i < 64 * 32; i += 256) {
            int row = i >> 5, c4 = i & 31;
            float4 kv = ((const float4*)kp)[i];
            int base = row * 129 + c4 * 4;
            Ks[base + 0] = kv.x; Ks[base + 1] = kv.y;
            Ks[base + 2] = kv.z; Ks[base + 3] = kv.w;
            ((float4*)Vs)[i] = ((const float4*)vp)[i];
        }
        __syncthreads();

        // scores S = Q K^T for this warp's 8 rows x lane's 2 cols
        float s0[8], s1[8];
        #pragma unroll
        for (int r = 0; r < 8; r++) { s0[r] = 0.f; s1[r] = 0.f; }
        const float* qrow = Qs + (w * 8) * 128;
        const float* k0p = Ks + l * 129;
        const float* k1p = Ks + (l + 32) * 129;
        #pragma unroll 4
        for (int kk = 0; kk < 128; kk++) {
            float k0 = k0p[kk];
            float k1 = k1p[kk];
            #pragma unroll
            for (int r = 0; r < 8; r++) {
                float qv = qrow[r * 128 + kk];
                s0[r] += qv * k0;
                s1[r] += qv * k1;
            }
        }

        int c0 = kt * 64 + l;
        int c1 = kt * 64 + l + 32;
        #pragma unroll
        for (int r = 0; r < 8; r++) {
            int row = qt * 64 + w * 8 + r;
            float v0 = (c0 <= row && c0 < eff_i) ? s0[r] * scale : -1e9f;
            float v1 = (c1 <= row && c1 < eff_i) ? s1[r] * scale : -1e9f;
            float mx = fmaxf(v0, v1);
            #pragma unroll
            for (int off = 16; off; off >>= 1)
                mx = fmaxf(mx, __shfl_xor_sync(0xffffffffu, mx, off));
            float mnew = fmaxf(m[r], mx);
            float corr = __expf(m[r] - mnew);
            float p0 = __expf(v0 - mnew);
            float p1 = __expf(v1 - mnew);
            float ps = p0 + p1;
            #pragma unroll
            for (int off = 16; off; off >>= 1)
                ps += __shfl_xor_sync(0xffffffffu, ps, off);
            lsum[r] = lsum[r] * corr + ps;
            m[r] = mnew;
            o[r][0] *= corr; o[r][1] *= corr; o[r][2] *= corr; o[r][3] *= corr;
            Ps[(w * 8 + r) * 64 + l]      = p0;
            Ps[(w * 8 + r) * 64 + l + 32] = p1;
        }
        __syncwarp();

        // O += P @ V
        #pragma unroll 2
        for (int c = 0; c < 64; c++) {
            float vv0 = Vs[c * 128 + l];
            float vv1 = Vs[c * 128 + l + 32];
            float vv2 = Vs[c * 128 + l + 64];
            float vv3 = Vs[c * 128 + l + 96];
            #pragma unroll
            for (int r = 0; r < 8; r++) {
                float p = Ps[(w * 8 + r) * 64 + c];
                o[r][0] += p * vv0;
                o[r][1] += p * vv1;
                o[r][2] += p * vv2;
                o[r][3] += p * vv3;
            }
        }
    }

    // write AO[token][h*128 + d]
    #pragma unroll
    for (int r = 0; r < 8; r++) {
        float inv = 1.0f / lsum[r];
        int srow = qt * 64 + w * 8 + r;
        float* op = AO + ((size_t)(b * S_ + srow)) * (NH_ * HD_) + h * HD_;
        op[l]      = o[r][0] * inv;
        op[l + 32] = o[r][1] * inv;
        op[l + 64] = o[r][2] * inv;
        op[l + 96] = o[r][3] * inv;
    }
}

// ---------------- launcher ----------------
extern "C" void kernel_launch(void* const* d_in, const int* in_sizes, int n_in,
                              void* d_out, int out_size)
{
    const float* x       = (const float*)d_in[0];
    const float* cosb    = (const float*)d_in[1];
    const float* sinb    = (const float*)d_in[2];
    const float* mask    = (const float*)d_in[3];
    const float* q_w     = (const float*)d_in[4];
    const float* q_b     = (const float*)d_in[5];
    const float* k_w     = (const float*)d_in[6];
    const float* k_b     = (const float*)d_in[7];
    const float* v_w     = (const float*)d_in[8];
    const float* v_b     = (const float*)d_in[9];
    const float* q_gamma = (const float*)d_in[10];
    const float* k_gamma = (const float*)d_in[11];
    const float* o_w     = (const float*)d_in[12];
    float* out = (float*)d_out;

    float* scratch = nullptr;
    cudaGetSymbolAddress((void**)&scratch, g_scratch);
    float* gq   = scratch + OFF_GQ;
    float* gk   = scratch + OFF_GK;
    float* gv   = scratch + OFF_GV;
    float* QT   = scratch + OFF_QT;
    float* KT   = scratch + OFF_KT;
    float* VT   = scratch + OFF_VT;
    float* AO   = scratch + OFF_AO;
    float* geff = scratch + OFF_EFF;

    cudaFuncSetAttribute(attn_kernel, cudaFuncAttributeMaxDynamicSharedMemorySize, ATTN_SMEM);

    eff_kernel<<<B_, 256>>>(mask, geff);

    sgemm_bias_kernel<<<dim3(16, 16), 256>>>(x, q_w, q_b, gq, TOK, NH_ * HD_, HID_);
    sgemm_bias_kernel<<<dim3(2, 16),  256>>>(x, k_w, k_b, gk, TOK, NKV_ * HD_, HID_);
    sgemm_bias_kernel<<<dim3(2, 16),  256>>>(x, v_w, v_b, gv, TOK, NKV_ * HD_, HID_);

    post_kernel<<<dim3(20, TOK), 128>>>(gq, gk, gv, cosb, sinb, mask,
                                        q_gamma, k_gamma, QT, KT, VT);

    attn_kernel<<<dim3(S_ / 64, NH_, B_), 256, ATTN_SMEM>>>(QT, KT, VT, geff, AO);

    sgemm_bias_kernel<<<dim3(16, 16), 256>>>(AO, o_w, nullptr, out, TOK, NH_ * HD_, HID_);
}

// round 3
// speedup vs baseline: 1.5466x; 1.5466x over previous
#include <cuda_runtime.h>
#include <cuda_bf16.h>
#include <math.h>
#include <stdint.h>

#define B_   2
#define S_   1024
#define HID_ 2048
#define NH_  16
#define NKV_ 2
#define HD_  128
#define G_   (NH_/NKV_)
#define TOK  (B_*S_)

#define KPRIME 6144        // 3 * 2048  (K' for 3-term bf16 split)
#define NQKV   2560

// ---------------- scratch ----------------
#define OFF_GQKV 0                        // TOK*2560          = 5242880
#define OFF_QT   5242880                  // 4194304
#define OFF_KT   9437184                  // 524288
#define OFF_VT   9961472                  // 524288
#define OFF_AO   10485760                 // 4194304
#define OFF_EFF  14680064                 // 2
#define OFF_BIAS 14680066                 // 2560
#define OFF_APK  14682628                 // 2048*6144 bf16 = 6291456 floats
#define OFF_BQKV 20974084                 // 2560*6144 bf16 = 7864320 floats
#define OFF_BOW  28838404                 // 2048*6144 bf16 = 6291456 floats
#define SCRATCH_F 35129860
__device__ __align__(256) float g_scratch[SCRATCH_F];

// ---------------- helpers ----------------
__device__ __forceinline__ uint32_t smem_u32(const void* p) {
    uint32_t a;
    asm("{ .reg .u64 t; cvta.to.shared.u64 t, %1; cvt.u32.u64 %0, t; }" : "=r"(a) : "l"(p));
    return a;
}
__device__ __forceinline__ void split_bf16(float f, unsigned short& h, unsigned short& l) {
    __nv_bfloat16 hb = __float2bfloat16_rn(f);
    float r = f - __bfloat162float(hb);
    __nv_bfloat16 lb = __float2bfloat16_rn(r);
    h = __bfloat16_as_ushort(hb);
    l = __bfloat16_as_ushort(lb);
}
__device__ __forceinline__ uint32_t pack2(unsigned short a, unsigned short b) {
    return (uint32_t)a | ((uint32_t)b << 16);
}
__device__ __forceinline__ void cp_async16(uint32_t saddr, const void* gaddr) {
    asm volatile("cp.async.cg.shared.global [%0], [%1], 16;" :: "r"(saddr), "l"(gaddr));
}
__device__ __forceinline__ void cp_commit() {
    asm volatile("cp.async.commit_group;");
}
template <int N>
__device__ __forceinline__ void cp_wait() {
    asm volatile("cp.async.wait_group %0;" :: "n"(N));
}
__device__ __forceinline__ void ldsm_x4(uint32_t* f, uint32_t addr) {
    asm volatile("ldmatrix.sync.aligned.m8n8.x4.shared.b16 {%0,%1,%2,%3}, [%4];"
                 : "=r"(f[0]), "=r"(f[1]), "=r"(f[2]), "=r"(f[3]) : "r"(addr));
}
__device__ __forceinline__ void mma_16816(float* c, const uint32_t* a, uint32_t b0, uint32_t b1) {
    asm volatile(
        "mma.sync.aligned.m16n8k16.row.col.f32.bf16.bf16.f32 "
        "{%0,%1,%2,%3}, {%4,%5,%6,%7}, {%8,%9}, {%0,%1,%2,%3};"
        : "+f"(c[0]), "+f"(c[1]), "+f"(c[2]), "+f"(c[3])
        : "r"(a[0]), "r"(a[1]), "r"(a[2]), "r"(a[3]), "r"(b0), "r"(b1));
}

// ---------------- eff[b] = sum_s mask[b][s] ----------------
__global__ void eff_kernel(const float* __restrict__ mask, float* __restrict__ eff) {
    int b = blockIdx.x;
    float s = 0.f;
    for (int i = threadIdx.x; i < S_; i += blockDim.x) s += mask[b * S_ + i];
    #pragma unroll
    for (int off = 16; off; off >>= 1) s += __shfl_xor_sync(0xffffffffu, s, off);
    __shared__ float red[8];
    if ((threadIdx.x & 31) == 0) red[threadIdx.x >> 5] = s;
    __syncthreads();
    if (threadIdx.x == 0) {
        float t = 0.f;
        for (int i = 0; i < (int)(blockDim.x >> 5); i++) t += red[i];
        eff[b] = t;
    }
}

// ---------------- bias concat ----------------
__global__ void biascat_kernel(const float* __restrict__ qb, const float* __restrict__ kb,
                               const float* __restrict__ vb, float* __restrict__ o) {
    int i = blockIdx.x * 256 + threadIdx.x;
    if (i < 2048) o[i] = qb[i];
    else if (i < 2304) o[i] = kb[i - 2048];
    else if (i < 2560) o[i] = vb[i - 2304];
}

// ---------------- pack activations: X [2048 x 2048] f32 -> [M][K'] bf16 [Ah|Al|Ah] ----------------
__global__ void __launch_bounds__(256) convA_kernel(const float* __restrict__ X,
                                                    __nv_bfloat16* __restrict__ Ap) {
    int g = blockIdx.x * 256 + threadIdx.x;
    int m = g >> 8;
    int kg = (g & 255) << 3;
    const float* xp = X + ((size_t)m << 11) + kg;
    float f[8];
    *(float4*)f       = *(const float4*)xp;
    *(float4*)(f + 4) = *(const float4*)(xp + 4);
    unsigned short h[8], l[8];
    #pragma unroll
    for (int i = 0; i < 8; i++) split_bf16(f[i], h[i], l[i]);
    uint4 Hi = make_uint4(pack2(h[0],h[1]), pack2(h[2],h[3]), pack2(h[4],h[5]), pack2(h[6],h[7]));
    uint4 Lo = make_uint4(pack2(l[0],l[1]), pack2(l[2],l[3]), pack2(l[4],l[5]), pack2(l[6],l[7]));
    __nv_bfloat16* base = Ap + (size_t)m * KPRIME;
    *(uint4*)(base + kg)        = Hi;
    *(uint4*)(base + 2048 + kg) = Lo;
    *(uint4*)(base + 4096 + kg) = Hi;
}

// ---------------- pack weights (transposed): W [2048(K) x N] f32 -> rows (noff+n) of [N'][K'] bf16 [Bh|Bh|Bl] ----------------
__global__ void __launch_bounds__(256) convB_kernel(const float* __restrict__ W,
                                                    __nv_bfloat16* __restrict__ Bp,
                                                    int N, int noff) {
    __shared__ float s[32][33];
    int n0 = blockIdx.x << 5, k0 = blockIdx.y << 5;
    int tid = threadIdx.x;
    #pragma unroll
    for (int p = 0; p < 4; p++) {
        int e = tid + p * 256;
        int ki = e >> 5, ni = e & 31;
        s[ki][ni] = W[(size_t)(k0 + ki) * N + n0 + ni];
    }
    __syncthreads();
    if (tid < 128) {
        int ni = tid >> 2, kg = (tid & 3) << 3;
        unsigned short h[8], l[8];
        #pragma unroll
        for (int j = 0; j < 8; j++) split_bf16(s[kg + j][ni], h[j], l[j]);
        uint4 Hi = make_uint4(pack2(h[0],h[1]), pack2(h[2],h[3]), pack2(h[4],h[5]), pack2(h[6],h[7]));
        uint4 Lo = make_uint4(pack2(l[0],l[1]), pack2(l[2],l[3]), pack2(l[4],l[5]), pack2(l[6],l[7]));
        __nv_bfloat16* base = Bp + (size_t)(noff + n0 + ni) * KPRIME + k0;
        *(uint4*)(base + kg)        = Hi;
        *(uint4*)(base + 2048 + kg) = Hi;
        *(uint4*)(base + 4096 + kg) = Lo;
    }
}

// ---------------- HMMA bf16 GEMM: C[M, Ntot] = A[M,K'] @ B[Ntot,K']^T (+bias) ----------------
// BM=128, BN=128, BK=32, 256 threads (8 warps 2x4), warp tile 64x32, 4-stage cp.async.
#define BKC 32
#define STAGE_B 16384              // 8KB A + 8KB B
#define GEMM_SMEM (4 * STAGE_B)    // 64KB
#define KITERS (KPRIME / BKC)      // 192

__device__ __forceinline__ void stage_load(uint32_t sbase, int stage,
                                           const __nv_bfloat16* Ag, const __nv_bfloat16* Bg,
                                           int k0, int lrow, int lchunk) {
    uint32_t sa = sbase + stage * STAGE_B;
    #pragma unroll
    for (int i = 0; i < 2; i++) {
        int row = lrow + i * 64;
        uint32_t sw = (uint32_t)((lchunk ^ ((row >> 1) & 3)) << 4);
        cp_async16(sa + row * 64 + sw,        Ag + (size_t)row * KPRIME + k0 + lchunk * 8);
        cp_async16(sa + 8192 + row * 64 + sw, Bg + (size_t)row * KPRIME + k0 + lchunk * 8);
    }
}

__global__ void __launch_bounds__(256, 1) gemm_mma_kernel(
    const __nv_bfloat16* __restrict__ A,
    const __nv_bfloat16* __restrict__ Bm,
    const float* __restrict__ bias,
    float* __restrict__ C, int Ntot)
{
    extern __shared__ char smc[];
    uint32_t sbase = smem_u32(smc);

    const int tid = threadIdx.x;
    const int mt = blockIdx.y, nt = blockIdx.x;
    const int warp = tid >> 5, lane = tid & 31;
    const int wm = warp >> 2, wn = warp & 3;

    const __nv_bfloat16* Ag = A  + (size_t)(mt * 128) * KPRIME;
    const __nv_bfloat16* Bg = Bm + (size_t)(nt * 128) * KPRIME;

    const int lrow = tid >> 2;     // 0..63
    const int lchunk = tid & 3;    // 16B chunk within 64B row

    // ldmatrix per-lane address components
    const int arow = wm * 64 + ((lane >> 3) & 1) * 8 + (lane & 7);
    const int achi = (lane >> 4) & 1;                 // A k-chunk hi bit
    const uint32_t asw = (uint32_t)((arow >> 1) & 3);
    const uint32_t abase = (uint32_t)(arow * 64);

    const int brow = wn * 32 + ((lane >> 4) & 1) * 8 + (lane & 7);
    const int bclo = (lane >> 3) & 1;                 // B k-chunk lo bit
    const uint32_t bsw = (uint32_t)((brow >> 1) & 3);
    const uint32_t bbase = (uint32_t)(brow * 64);

    float acc[16][4];
    #pragma unroll
    for (int i = 0; i < 16; i++)
        #pragma unroll
        for (int j = 0; j < 4; j++) acc[i][j] = 0.f;

    // prologue: 3 stages
    #pragma unroll
    for (int s = 0; s < 3; s++) {
        stage_load(sbase, s, Ag, Bg, s * BKC, lrow, lchunk);
        cp_commit();
    }

    for (int kt = 0; kt < KITERS; kt++) {
        cp_wait<2>();
        __syncthreads();

        // prefetch stage kt+3
        int nxt = kt + 3;
        if (nxt < KITERS) stage_load(sbase, nxt & 3, Ag, Bg, nxt * BKC, lrow, lchunk);
        cp_commit();

        uint32_t sa = sbase + (kt & 3) * STAGE_B;
        uint32_t sb = sa + 8192;

        #pragma unroll
        for (int ks = 0; ks < 2; ks++) {
            uint32_t af[4][4];
            #pragma unroll
            for (int m = 0; m < 4; m++)
                ldsm_x4(af[m], sa + abase + m * 1024 + ((((uint32_t)(ks * 2 + achi)) ^ asw) << 4));
            uint32_t bf0[4], bf1[4];
            ldsm_x4(bf0, sb + bbase +        ((((uint32_t)(ks * 2 + bclo)) ^ bsw) << 4));
            ldsm_x4(bf1, sb + bbase + 1024 + ((((uint32_t)(ks * 2 + bclo)) ^ bsw) << 4));
            #pragma unroll
            for (int m = 0; m < 4; m++) {
                mma_16816(acc[m * 4 + 0], af[m], bf0[0], bf0[1]);
                mma_16816(acc[m * 4 + 1], af[m], bf0[2], bf0[3]);
                mma_16816(acc[m * 4 + 2], af[m], bf1[0], bf1[1]);
                mma_16816(acc[m * 4 + 3], af[m], bf1[2], bf1[3]);
            }
        }
    }

    // epilogue
    #pragma unroll
    for (int n = 0; n < 4; n++) {
        int col = nt * 128 + wn * 32 + n * 8 + (lane & 3) * 2;
        float b0 = bias ? bias[col]     : 0.f;
        float b1 = bias ? bias[col + 1] : 0.f;
        #pragma unroll
        for (int m = 0; m < 4; m++) {
            int row = mt * 128 + wm * 64 + m * 16 + (lane >> 2);
            float2 v0 = make_float2(acc[m * 4 + n][0] + b0, acc[m * 4 + n][1] + b1);
            float2 v1 = make_float2(acc[m * 4 + n][2] + b0, acc[m * 4 + n][3] + b1);
            *(float2*)(C + (size_t)row * Ntot + col)       = v0;
            *(float2*)(C + (size_t)(row + 8) * Ntot + col) = v1;
        }
    }
}

// ---------------- RMSNorm + sectioned RoPE + mask ----------------
__global__ void post_kernel(
    const float* __restrict__ gqkv,
    const float* __restrict__ cosb, const float* __restrict__ sinb,
    const float* __restrict__ mask,
    const float* __restrict__ q_gamma, const float* __restrict__ k_gamma,
    float* __restrict__ Qo, float* __restrict__ Ko, float* __restrict__ Vo)
{
    int unit = blockIdx.x;
    int t = blockIdx.y;
    int b = t >> 10, s = t & (S_ - 1);
    int d = threadIdx.x;
    float mval = mask[t];
    const float* rowp = gqkv + (size_t)t * NQKV;

    if (unit >= 18) {
        int kh = unit - 18;
        float v = rowp[2304 + kh * HD_ + d];
        Vo[(((size_t)(b * NKV_ + kh)) * S_ + s) * HD_ + d] = v * mval;
        return;
    }

    float val;
    const float* gamma;
    if (unit < 16) { val = rowp[unit * HD_ + d]; gamma = q_gamma; }
    else           { val = rowp[2048 + (unit - 16) * HD_ + d]; gamma = k_gamma; }

    float v2 = val * val;
    #pragma unroll
    for (int off = 16; off; off >>= 1) v2 += __shfl_xor_sync(0xffffffffu, v2, off);
    __shared__ float red[4];
    __shared__ float sh[128];
    if ((d & 31) == 0) red[d >> 5] = v2;
    __syncthreads();
    float tot = red[0] + red[1] + red[2] + red[3];
    float nv = gamma[d] * val * rsqrtf(tot * (1.0f / HD_) + 1e-6f);
    sh[d] = nv;
    __syncthreads();
    float partner = (d < 64) ? -sh[d + 64] : sh[d - 64];

    int sec = (d < 16) ? 0 : (d < 40) ? 1 : (d < 64) ? 2 : (d < 80) ? 0 : (d < 104) ? 1 : 2;
    size_t ci = (((size_t)sec * B_ + b) * S_ + s) * HD_ + d;
    float o = nv * cosb[ci] + partner * sinb[ci];

    if (unit < 16) {
        Qo[(((size_t)(b * NH_ + unit)) * S_ + s) * HD_ + d] = o;
    } else {
        Ko[(((size_t)(b * NKV_ + (unit - 16))) * S_ + s) * HD_ + d] = o * mval;
    }
}

// ---------------- fp32 flash attention, causal, GQA ----------------
#define ATTN_SMEM ((64*128 + 64*129 + 64*128 + 64*64) * 4)
__global__ void __launch_bounds__(256, 1) attn_kernel(
    const float* __restrict__ Q, const float* __restrict__ K, const float* __restrict__ V,
    const float* __restrict__ eff, float* __restrict__ AO)
{
    extern __shared__ float sm[];
    float* Qs = sm;
    float* Ks = Qs + 64 * 128;
    float* Vs = Ks + 64 * 129;
    float* Ps = Vs + 64 * 128;

    int qt = blockIdx.x;
    int h  = blockIdx.y;
    int b  = blockIdx.z;
    int kvh = h / G_;

    int tid = threadIdx.x;
    int w = tid >> 5;
    int l = tid & 31;

    const float* Qg = Q + (((size_t)(b * NH_ + h) * S_) + qt * 64) * HD_;
    const float* Kg = K + ((size_t)(b * NKV_ + kvh) * S_) * HD_;
    const float* Vg = V + ((size_t)(b * NKV_ + kvh) * S_) * HD_;

    for (int i = tid; i < 64 * 32; i += 256)
        ((float4*)Qs)[i] = ((const float4*)Qg)[i];

    float m[8], lsum[8], o[8][4];
    #pragma unroll
    for (int r = 0; r < 8; r++) {
        m[r] = -1e30f; lsum[r] = 0.f;
        o[r][0] = o[r][1] = o[r][2] = o[r][3] = 0.f;
    }

    int eff_i = (int)(eff[b] + 0.5f);
    const float scale = 0.08838834764831845f;

    for (int kt = 0; kt <= qt; kt++) {
        __syncthreads();
        const float* kp = Kg + (size_t)kt * 64 * HD_;
        const float* vp = Vg + (size_t)kt * 64 * HD_;
        for (int i = tid; i < 64 * 32; i += 256) {
            int row = i >> 5, c4 = i & 31;
            float4 kv = ((const float4*)kp)[i];
            int base = row * 129 + c4 * 4;
            Ks[base + 0] = kv.x; Ks[base + 1] = kv.y;
            Ks[base + 2] = kv.z; Ks[base + 3] = kv.w;
            ((float4*)Vs)[i] = ((const float4*)vp)[i];
        }
        __syncthreads();

        float s0[8], s1[8];
        #pragma unroll
        for (int r = 0; r < 8; r++) { s0[r] = 0.f; s1[r] = 0.f; }
        const float* qrow = Qs + (w * 8) * 128;
        const float* k0p = Ks + l * 129;
        const float* k1p = Ks + (l + 32) * 129;
        #pragma unroll 4
        for (int kk = 0; kk < 128; kk++) {
            float k0 = k0p[kk];
            float k1 = k1p[kk];
            #pragma unroll
            for (int r = 0; r < 8; r++) {
                float qv = qrow[r * 128 + kk];
                s0[r] += qv * k0;
                s1[r] += qv * k1;
            }
        }

        int c0 = kt * 64 + l;
        int c1 = kt * 64 + l + 32;
        #pragma unroll
        for (int r = 0; r < 8; r++) {
            int row = qt * 64 + w * 8 + r;
            float v0 = (c0 <= row && c0 < eff_i) ? s0[r] * scale : -1e9f;
            float v1 = (c1 <= row && c1 < eff_i) ? s1[r] * scale : -1e9f;
            float mx = fmaxf(v0, v1);
            #pragma unroll
            for (int off = 16; off; off >>= 1)
                mx = fmaxf(mx, __shfl_xor_sync(0xffffffffu, mx, off));
            float mnew = fmaxf(m[r], mx);
            float corr = __expf(m[r] - mnew);
            float p0 = __expf(v0 - mnew);
            float p1 = __expf(v1 - mnew);
            float ps = p0 + p1;
            #pragma unroll
            for (int off = 16; off; off >>= 1)
                ps += __shfl_xor_sync(0xffffffffu, ps, off);
            lsum[r] = lsum[r] * corr + ps;
            m[r] = mnew;
            o[r][0] *= corr; o[r][1] *= corr; o[r][2] *= corr; o[r][3] *= corr;
            Ps[(w * 8 + r) * 64 + l]      = p0;
            Ps[(w * 8 + r) * 64 + l + 32] = p1;
        }
        __syncwarp();

        #pragma unroll 2
        for (int c = 0; c < 64; c++) {
            float vv0 = Vs[c * 128 + l];
            float vv1 = Vs[c * 128 + l + 32];
            float vv2 = Vs[c * 128 + l + 64];
            float vv3 = Vs[c * 128 + l + 96];
            #pragma unroll
            for (int r = 0; r < 8; r++) {
                float p = Ps[(w * 8 + r) * 64 + c];
                o[r][0] += p * vv0;
                o[r][1] += p * vv1;
                o[r][2] += p * vv2;
                o[r][3] += p * vv3;
            }
        }
    }

    #pragma unroll
    for (int r = 0; r < 8; r++) {
        float inv = 1.0f / lsum[r];
        int srow = qt * 64 + w * 8 + r;
        float* op = AO + ((size_t)(b * S_ + srow)) * (NH_ * HD_) + h * HD_;
        op[l]      = o[r][0] * inv;
        op[l + 32] = o[r][1] * inv;
        op[l + 64] = o[r][2] * inv;
        op[l + 96] = o[r][3] * inv;
    }
}

// ---------------- launcher ----------------
extern "C" void kernel_launch(void* const* d_in, const int* in_sizes, int n_in,
                              void* d_out, int out_size)
{
    const float* x       = (const float*)d_in[0];
    const float* cosb    = (const float*)d_in[1];
    const float* sinb    = (const float*)d_in[2];
    const float* mask    = (const float*)d_in[3];
    const float* q_w     = (const float*)d_in[4];
    const float* q_b     = (const float*)d_in[5];
    const float* k_w     = (const float*)d_in[6];
    const float* k_b     = (const float*)d_in[7];
    const float* v_w     = (const float*)d_in[8];
    const float* v_b     = (const float*)d_in[9];
    const float* q_gamma = (const float*)d_in[10];
    const float* k_gamma = (const float*)d_in[11];
    const float* o_w     = (const float*)d_in[12];
    float* out = (float*)d_out;

    float* scratch = nullptr;
    cudaGetSymbolAddress((void**)&scratch, g_scratch);
    float* gqkv = scratch + OFF_GQKV;
    float* QT   = scratch + OFF_QT;
    float* KT   = scratch + OFF_KT;
    float* VT   = scratch + OFF_VT;
    float* AO   = scratch + OFF_AO;
    float* geff = scratch + OFF_EFF;
    float* bias = scratch + OFF_BIAS;
    __nv_bfloat16* Apack = (__nv_bfloat16*)(scratch + OFF_APK);
    __nv_bfloat16* Bqkv  = (__nv_bfloat16*)(scratch + OFF_BQKV);
    __nv_bfloat16* Bow   = (__nv_bfloat16*)(scratch + OFF_BOW);

    cudaFuncSetAttribute(attn_kernel, cudaFuncAttributeMaxDynamicSharedMemorySize, ATTN_SMEM);
    cudaFuncSetAttribute(gemm_mma_kernel, cudaFuncAttributeMaxDynamicSharedMemorySize, GEMM_SMEM);

    eff_kernel<<<B_, 256>>>(mask, geff);
    biascat_kernel<<<10, 256>>>(q_b, k_b, v_b, bias);

    convA_kernel<<<2048, 256>>>(x, Apack);
    convB_kernel<<<dim3(64, 64), 256>>>(q_w, Bqkv, 2048, 0);
    convB_kernel<<<dim3(8, 64),  256>>>(k_w, Bqkv, 256, 2048);
    convB_kernel<<<dim3(8, 64),  256>>>(v_w, Bqkv, 256, 2304);
    convB_kernel<<<dim3(64, 64), 256>>>(o_w, Bow, 2048, 0);

    gemm_mma_kernel<<<dim3(NQKV / 128, 16), 256, GEMM_SMEM>>>(Apack, Bqkv, bias, gqkv, NQKV);

    post_kernel<<<dim3(20, TOK), 128>>>(gqkv, cosb, sinb, mask, q_gamma, k_gamma, QT, KT, VT);
    attn_kernel<<<dim3(S_ / 64, NH_, B_), 256, ATTN_SMEM>>>(QT, KT, VT, geff, AO);

    convA_kernel<<<2048, 256>>>(AO, Apack);
    gemm_mma_kernel<<<dim3(16, 16), 256, GEMM_SMEM>>>(Apack, Bow, nullptr, out, 2048);
}

// round 4
// speedup vs baseline: 2.5616x; 1.6563x over previous
#include <cuda_runtime.h>
#include <cuda_bf16.h>
#include <math.h>
#include <stdint.h>

#define B_   2
#define S_   1024
#define HID_ 2048
#define NH_  16
#define NKV_ 2
#define HD_  128
#define G_   (NH_/NKV_)
#define TOK  (B_*S_)

#define KPRIME 6144        // 3 * 2048
#define NQKV   2560

// ---------------- scratch (floats) ----------------
#define OFF_GQKV 0                        // 5242880
#define OFF_EFF  5242880                  // 2
#define OFF_BIAS 5242884                  // 2560
#define OFF_APK  5245444                  // 2048*6144 bf16 = 6291456 floats
#define OFF_BQKV 11536900                 // 2560*6144 bf16 = 7864320 floats
#define OFF_BOW  19401220                 // 6291456 floats
#define OFF_QPK  25692676                 // 2*16*1024*256 bf16 = 4194304 floats
#define OFF_KPK  29886980                 // 524288 floats
#define OFF_VPK  30411268                 // 524288 floats
#define SCRATCH_F 30935560
__device__ __align__(256) float g_scratch[SCRATCH_F];

// ---------------- helpers ----------------
__device__ __forceinline__ uint32_t smem_u32(const void* p) {
    uint32_t a;
    asm("{ .reg .u64 t; cvta.to.shared.u64 t, %1; cvt.u32.u64 %0, t; }" : "=r"(a) : "l"(p));
    return a;
}
__device__ __forceinline__ void split_bf16(float f, unsigned short& h, unsigned short& l) {
    __nv_bfloat16 hb = __float2bfloat16_rn(f);
    float r = f - __bfloat162float(hb);
    __nv_bfloat16 lb = __float2bfloat16_rn(r);
    h = __bfloat16_as_ushort(hb);
    l = __bfloat16_as_ushort(lb);
}
__device__ __forceinline__ uint32_t pack2(unsigned short a, unsigned short b) {
    return (uint32_t)a | ((uint32_t)b << 16);
}
__device__ __forceinline__ void cp_async16(uint32_t saddr, const void* gaddr) {
    asm volatile("cp.async.cg.shared.global [%0], [%1], 16;" :: "r"(saddr), "l"(gaddr));
}
__device__ __forceinline__ void cp_commit() {
    asm volatile("cp.async.commit_group;");
}
template <int N>
__device__ __forceinline__ void cp_wait() {
    asm volatile("cp.async.wait_group %0;" :: "n"(N));
}
__device__ __forceinline__ void ldsm_x4(uint32_t* f, uint32_t addr) {
    asm volatile("ldmatrix.sync.aligned.m8n8.x4.shared.b16 {%0,%1,%2,%3}, [%4];"
                 : "=r"(f[0]), "=r"(f[1]), "=r"(f[2]), "=r"(f[3]) : "r"(addr));
}
__device__ __forceinline__ void ldsm_x4_t(uint32_t* f, uint32_t addr) {
    asm volatile("ldmatrix.sync.aligned.m8n8.x4.trans.shared.b16 {%0,%1,%2,%3}, [%4];"
                 : "=r"(f[0]), "=r"(f[1]), "=r"(f[2]), "=r"(f[3]) : "r"(addr));
}
__device__ __forceinline__ void mma_16816(float* c, const uint32_t* a, uint32_t b0, uint32_t b1) {
    asm volatile(
        "mma.sync.aligned.m16n8k16.row.col.f32.bf16.bf16.f32 "
        "{%0,%1,%2,%3}, {%4,%5,%6,%7}, {%8,%9}, {%0,%1,%2,%3};"
        : "+f"(c[0]), "+f"(c[1]), "+f"(c[2]), "+f"(c[3])
        : "r"(a[0]), "r"(a[1]), "r"(a[2]), "r"(a[3]), "r"(b0), "r"(b1));
}
// swizzle: 16B chunk index within 512B row; keep bit4 (hi/lo half) intact
__device__ __forceinline__ uint32_t csw(uint32_t c, uint32_t row) {
    return (c & 0x10u) | ((c ^ (row & 7u)) & 0x0Fu);
}

// ---------------- eff ----------------
__global__ void eff_kernel(const float* __restrict__ mask, float* __restrict__ eff) {
    int b = blockIdx.x;
    float s = 0.f;
    for (int i = threadIdx.x; i < S_; i += blockDim.x) s += mask[b * S_ + i];
    #pragma unroll
    for (int off = 16; off; off >>= 1) s += __shfl_xor_sync(0xffffffffu, s, off);
    __shared__ float red[8];
    if ((threadIdx.x & 31) == 0) red[threadIdx.x >> 5] = s;
    __syncthreads();
    if (threadIdx.x == 0) {
        float t = 0.f;
        for (int i = 0; i < (int)(blockDim.x >> 5); i++) t += red[i];
        eff[b] = t;
    }
}

// ---------------- bias concat ----------------
__global__ void biascat_kernel(const float* __restrict__ qb, const float* __restrict__ kb,
                               const float* __restrict__ vb, float* __restrict__ o) {
    int i = blockIdx.x * 256 + threadIdx.x;
    if (i < 2048) o[i] = qb[i];
    else if (i < 2304) o[i] = kb[i - 2048];
    else if (i < 2560) o[i] = vb[i - 2304];
}

// ---------------- pack activations X -> [Ah|Al|Ah] ----------------
__global__ void __launch_bounds__(256) convA_kernel(const float* __restrict__ X,
                                                    __nv_bfloat16* __restrict__ Ap) {
    int g = blockIdx.x * 256 + threadIdx.x;
    int m = g >> 8;
    int kg = (g & 255) << 3;
    const float* xp = X + ((size_t)m << 11) + kg;
    float f[8];
    *(float4*)f       = *(const float4*)xp;
    *(float4*)(f + 4) = *(const float4*)(xp + 4);
    unsigned short h[8], l[8];
    #pragma unroll
    for (int i = 0; i < 8; i++) split_bf16(f[i], h[i], l[i]);
    uint4 Hi = make_uint4(pack2(h[0],h[1]), pack2(h[2],h[3]), pack2(h[4],h[5]), pack2(h[6],h[7]));
    uint4 Lo = make_uint4(pack2(l[0],l[1]), pack2(l[2],l[3]), pack2(l[4],l[5]), pack2(l[6],l[7]));
    __nv_bfloat16* base = Ap + (size_t)m * KPRIME;
    *(uint4*)(base + kg)        = Hi;
    *(uint4*)(base + 2048 + kg) = Lo;
    *(uint4*)(base + 4096 + kg) = Hi;
}

// ---------------- pack weights (transposed) -> [Bh|Bh|Bl] ----------------
__global__ void __launch_bounds__(256) convB_kernel(const float* __restrict__ W,
                                                    __nv_bfloat16* __restrict__ Bp,
                                                    int N, int noff) {
    __shared__ float s[32][33];
    int n0 = blockIdx.x << 5, k0 = blockIdx.y << 5;
    int tid = threadIdx.x;
    #pragma unroll
    for (int p = 0; p < 4; p++) {
        int e = tid + p * 256;
        int ki = e >> 5, ni = e & 31;
        s[ki][ni] = W[(size_t)(k0 + ki) * N + n0 + ni];
    }
    __syncthreads();
    if (tid < 128) {
        int ni = tid >> 2, kg = (tid & 3) << 3;
        unsigned short h[8], l[8];
        #pragma unroll
        for (int j = 0; j < 8; j++) split_bf16(s[kg + j][ni], h[j], l[j]);
        uint4 Hi = make_uint4(pack2(h[0],h[1]), pack2(h[2],h[3]), pack2(h[4],h[5]), pack2(h[6],h[7]));
        uint4 Lo = make_uint4(pack2(l[0],l[1]), pack2(l[2],l[3]), pack2(l[4],l[5]), pack2(l[6],l[7]));
        __nv_bfloat16* base = Bp + (size_t)(noff + n0 + ni) * KPRIME + k0;
        *(uint4*)(base + kg)        = Hi;
        *(uint4*)(base + 2048 + kg) = Hi;
        *(uint4*)(base + 4096 + kg) = Lo;
    }
}

// ---------------- HMMA GEMM (same as R3, 2 CTAs/SM) ----------------
#define BKC 32
#define STAGE_B 16384
#define GEMM_SMEM (4 * STAGE_B)
#define KITERS (KPRIME / BKC)

__device__ __forceinline__ void stage_load(uint32_t sbase, int stage,
                                           const __nv_bfloat16* Ag, const __nv_bfloat16* Bg,
                                           int k0, int lrow, int lchunk) {
    uint32_t sa = sbase + stage * STAGE_B;
    #pragma unroll
    for (int i = 0; i < 2; i++) {
        int row = lrow + i * 64;
        uint32_t sw = (uint32_t)((lchunk ^ ((row >> 1) & 3)) << 4);
        cp_async16(sa + row * 64 + sw,        Ag + (size_t)row * KPRIME + k0 + lchunk * 8);
        cp_async16(sa + 8192 + row * 64 + sw, Bg + (size_t)row * KPRIME + k0 + lchunk * 8);
    }
}

__global__ void __launch_bounds__(256, 2) gemm_mma_kernel(
    const __nv_bfloat16* __restrict__ A,
    const __nv_bfloat16* __restrict__ Bm,
    const float* __restrict__ bias,
    float* __restrict__ C, int Ntot)
{
    extern __shared__ char smc[];
    uint32_t sbase = smem_u32(smc);

    const int tid = threadIdx.x;
    const int mt = blockIdx.y, nt = blockIdx.x;
    const int warp = tid >> 5, lane = tid & 31;
    const int wm = warp >> 2, wn = warp & 3;

    const __nv_bfloat16* Ag = A  + (size_t)(mt * 128) * KPRIME;
    const __nv_bfloat16* Bg = Bm + (size_t)(nt * 128) * KPRIME;

    const int lrow = tid >> 2;
    const int lchunk = tid & 3;

    const int arow = wm * 64 + ((lane >> 3) & 1) * 8 + (lane & 7);
    const int achi = (lane >> 4) & 1;
    const uint32_t asw = (uint32_t)((arow >> 1) & 3);
    const uint32_t abase = (uint32_t)(arow * 64);

    const int brow = wn * 32 + ((lane >> 4) & 1) * 8 + (lane & 7);
    const int bclo = (lane >> 3) & 1;
    const uint32_t bsw = (uint32_t)((brow >> 1) & 3);
    const uint32_t bbase = (uint32_t)(brow * 64);

    float acc[16][4];
    #pragma unroll
    for (int i = 0; i < 16; i++)
        #pragma unroll
        for (int j = 0; j < 4; j++) acc[i][j] = 0.f;

    #pragma unroll
    for (int s = 0; s < 3; s++) {
        stage_load(sbase, s, Ag, Bg, s * BKC, lrow, lchunk);
        cp_commit();
    }

    for (int kt = 0; kt < KITERS; kt++) {
        cp_wait<2>();
        __syncthreads();

        int nxt = kt + 3;
        if (nxt < KITERS) stage_load(sbase, nxt & 3, Ag, Bg, nxt * BKC, lrow, lchunk);
        cp_commit();

        uint32_t sa = sbase + (kt & 3) * STAGE_B;
        uint32_t sb = sa + 8192;

        #pragma unroll
        for (int ks = 0; ks < 2; ks++) {
            uint32_t af[4][4];
            #pragma unroll
            for (int m = 0; m < 4; m++)
                ldsm_x4(af[m], sa + abase + m * 1024 + ((((uint32_t)(ks * 2 + achi)) ^ asw) << 4));
            uint32_t bf0[4], bf1[4];
            ldsm_x4(bf0, sb + bbase +        ((((uint32_t)(ks * 2 + bclo)) ^ bsw) << 4));
            ldsm_x4(bf1, sb + bbase + 1024 + ((((uint32_t)(ks * 2 + bclo)) ^ bsw) << 4));
            #pragma unroll
            for (int m = 0; m < 4; m++) {
                mma_16816(acc[m * 4 + 0], af[m], bf0[0], bf0[1]);
                mma_16816(acc[m * 4 + 1], af[m], bf0[2], bf0[3]);
                mma_16816(acc[m * 4 + 2], af[m], bf1[0], bf1[1]);
                mma_16816(acc[m * 4 + 3], af[m], bf1[2], bf1[3]);
            }
        }
    }

    #pragma unroll
    for (int n = 0; n < 4; n++) {
        int col = nt * 128 + wn * 32 + n * 8 + (lane & 3) * 2;
        float b0 = bias ? bias[col]     : 0.f;
        float b1 = bias ? bias[col + 1] : 0.f;
        #pragma unroll
        for (int m = 0; m < 4; m++) {
            int row = mt * 128 + wm * 64 + m * 16 + (lane >> 2);
            float2 v0 = make_float2(acc[m * 4 + n][0] + b0, acc[m * 4 + n][1] + b1);
            float2 v1 = make_float2(acc[m * 4 + n][2] + b0, acc[m * 4 + n][3] + b1);
            *(float2*)(C + (size_t)row * Ntot + col)       = v0;
            *(float2*)(C + (size_t)(row + 8) * Ntot + col) = v1;
        }
    }
}

// ---------------- RMSNorm + RoPE + mask -> packed split-bf16 Q/K/V ----------------
__global__ void post_kernel(
    const float* __restrict__ gqkv,
    const float* __restrict__ cosb, const float* __restrict__ sinb,
    const float* __restrict__ mask,
    const float* __restrict__ q_gamma, const float* __restrict__ k_gamma,
    __nv_bfloat16* __restrict__ Qpk, __nv_bfloat16* __restrict__ Kpk,
    __nv_bfloat16* __restrict__ Vpk)
{
    int unit = blockIdx.x;
    int t = blockIdx.y;
    int b = t >> 10, s = t & (S_ - 1);
    int d = threadIdx.x;
    float mval = mask[t];
    const float* rowp = gqkv + (size_t)t * NQKV;

    if (unit >= 18) {
        int kh = unit - 18;
        float v = rowp[2304 + kh * HD_ + d] * mval;
        unsigned short hi, lo;
        split_bf16(v, hi, lo);
        __nv_bfloat16* vp = Vpk + ((size_t)(b * NKV_ + kh) * S_ + s) * 256;
        vp[d]       = __ushort_as_bfloat16(hi);
        vp[128 + d] = __ushort_as_bfloat16(lo);
        return;
    }

    float val;
    const float* gamma;
    if (unit < 16) { val = rowp[unit * HD_ + d]; gamma = q_gamma; }
    else           { val = rowp[2048 + (unit - 16) * HD_ + d]; gamma = k_gamma; }

    float v2 = val * val;
    #pragma unroll
    for (int off = 16; off; off >>= 1) v2 += __shfl_xor_sync(0xffffffffu, v2, off);
    __shared__ float red[4];
    __shared__ float sh[128];
    if ((d & 31) == 0) red[d >> 5] = v2;
    __syncthreads();
    float tot = red[0] + red[1] + red[2] + red[3];
    float nv = gamma[d] * val * rsqrtf(tot * (1.0f / HD_) + 1e-6f);
    sh[d] = nv;
    __syncthreads();
    float partner = (d < 64) ? -sh[d + 64] : sh[d - 64];

    int sec = (d < 16) ? 0 : (d < 40) ? 1 : (d < 64) ? 2 : (d < 80) ? 0 : (d < 104) ? 1 : 2;
    size_t ci = (((size_t)sec * B_ + b) * S_ + s) * HD_ + d;
    float o = nv * cosb[ci] + partner * sinb[ci];

    unsigned short hi, lo;
    if (unit < 16) {
        split_bf16(o, hi, lo);
        __nv_bfloat16* qp = Qpk + ((size_t)(b * NH_ + unit) * S_ + s) * 256;
        qp[d]       = __ushort_as_bfloat16(hi);
        qp[128 + d] = __ushort_as_bfloat16(lo);
    } else {
        split_bf16(o * mval, hi, lo);
        __nv_bfloat16* kp = Kpk + ((size_t)(b * NKV_ + (unit - 16)) * S_ + s) * 256;
        kp[d]       = __ushort_as_bfloat16(hi);
        kp[128 + d] = __ushort_as_bfloat16(lo);
    }
}

// ---------------- tensor-core flash attention ----------------
// CTA = 128 q-rows x (qt+1)*128 kv, tiles of 64 kv. 8 warps x 16 rows.
// smem: 2 stages x (K 32KB + V 32KB) = 128KB. Q staged in stage0 first.
#define ATTN_SMEM2 131072

__global__ void __launch_bounds__(256, 1) attn_tc_kernel(
    const __nv_bfloat16* __restrict__ Qpk, const __nv_bfloat16* __restrict__ Kpk,
    const __nv_bfloat16* __restrict__ Vpk, const float* __restrict__ eff,
    __nv_bfloat16* __restrict__ Apk)
{
    extern __shared__ char smc[];
    uint32_t sbase = smem_u32(smc);

    int bid = blockIdx.x;
    int qt = 7 - (bid >> 5);
    int rem = bid & 31;
    int h = rem >> 1, b = rem & 1;
    int kvh = h / G_;
    int tid = threadIdx.x, warp = tid >> 5, lane = tid & 31;

    const __nv_bfloat16* Qg = Qpk + ((size_t)(b * NH_ + h) * S_ + qt * 128) * 256;
    const __nv_bfloat16* Kg = Kpk + ((size_t)(b * NKV_ + kvh) * S_) * 256;
    const __nv_bfloat16* Vg = Vpk + ((size_t)(b * NKV_ + kvh) * S_) * 256;

    // ---- load Q into stage0 ----
    #pragma unroll
    for (int it = 0; it < 16; it++) {
        int idx = it * 256 + tid;
        int r = idx >> 5, c = idx & 31;
        cp_async16(sbase + r * 512 + csw(c, r) * 16, Qg + (size_t)r * 256 + c * 8);
    }
    cp_commit();
    cp_wait<0>();
    __syncthreads();

    // ---- extract Q fragments ----
    uint32_t qh[8][4], ql[8][4];
    {
        int row = warp * 16 + ((lane >> 3) & 1) * 8 + (lane & 7);
        uint32_t roff = sbase + row * 512;
        uint32_t r7 = row & 7;
        int chi = (lane >> 4) & 1;
        #pragma unroll
        for (int j = 0; j < 8; j++) {
            uint32_t ch = 2 * j + chi;
            ldsm_x4(qh[j], roff + ((ch ^ r7) & 15u) * 16);
            ldsm_x4(ql[j], roff + (16u | ((ch ^ r7) & 15u)) * 16);
        }
    }
    __syncthreads();

    int ntiles = 2 * (qt + 1);
    int eff_i = (int)(eff[b] + 0.5f);

    // prologue: tiles 0 and 1
    #pragma unroll
    for (int pt = 0; pt < 2; pt++) {
        #pragma unroll
        for (int it = 0; it < 8; it++) {
            int idx = it * 256 + tid;
            int r = idx >> 5, c = idx & 31;
            uint32_t dsw = (uint32_t)pt * 65536 + r * 512 + csw(c, r) * 16;
            size_t go = (size_t)(pt * 64 + r) * 256 + c * 8;
            cp_async16(sbase + dsw,         Kg + go);
            cp_async16(sbase + 32768 + dsw, Vg + go);
        }
        cp_commit();
    }

    float m0 = -1e30f, m1 = -1e30f, ls0 = 0.f, ls1 = 0.f;
    float o[16][4];
    #pragma unroll
    for (int i = 0; i < 16; i++) { o[i][0] = o[i][1] = o[i][2] = o[i][3] = 0.f; }

    const float scale = 0.08838834764831845f;
    int row0 = qt * 128 + warp * 16 + (lane >> 2);
    int colb = (lane & 3) * 2;
    int krbase = ((lane >> 4) & 1) * 8 + (lane & 7);
    int kchi = (lane >> 3) & 1;
    int vrbase = ((lane >> 3) & 1) * 8 + (lane & 7);
    int vchi = (lane >> 4) & 1;

    for (int kt = 0; kt < ntiles; kt++) {
        cp_wait<1>();
        __syncthreads();
        uint32_t sk = sbase + (uint32_t)(kt & 1) * 65536;
        uint32_t sv = sk + 32768;

        // ---- S = Qh Kh + Ql Kh + Qh Kl ----
        float s[8][4];
        #pragma unroll
        for (int i = 0; i < 8; i++) { s[i][0] = s[i][1] = s[i][2] = s[i][3] = 0.f; }

        #pragma unroll
        for (int nbp = 0; nbp < 4; nbp++) {
            int krow = nbp * 16 + krbase;
            uint32_t kroff = sk + krow * 512;
            uint32_t kr7 = krow & 7;
            #pragma unroll
            for (int j = 0; j < 8; j++) {
                uint32_t ch = 2 * j + kchi;
                uint32_t khf[4], klf[4];
                ldsm_x4(khf, kroff + ((ch ^ kr7) & 15u) * 16);
                ldsm_x4(klf, kroff + (16u | ((ch ^ kr7) & 15u)) * 16);
                mma_16816(s[2*nbp],   qh[j], khf[0], khf[1]);
                mma_16816(s[2*nbp+1], qh[j], khf[2], khf[3]);
                mma_16816(s[2*nbp],   ql[j], khf[0], khf[1]);
                mma_16816(s[2*nbp+1], ql[j], khf[2], khf[3]);
                mma_16816(s[2*nbp],   qh[j], klf[0], klf[1]);
                mma_16816(s[2*nbp+1], qh[j], klf[2], klf[3]);
            }
        }

        // ---- mask + online softmax ----
        float mx0 = -1e30f, mx1 = -1e30f;
        #pragma unroll
        for (int nb = 0; nb < 8; nb++) {
            int c0 = kt * 64 + nb * 8 + colb;
            #pragma unroll
            for (int e = 0; e < 2; e++) {
                int cc = c0 + e;
                float v0 = (cc <= row0     && cc < eff_i) ? s[nb][e]   * scale : -1e9f;
                float v1 = (cc <= row0 + 8 && cc < eff_i) ? s[nb][2+e] * scale : -1e9f;
                s[nb][e] = v0; s[nb][2+e] = v1;
                mx0 = fmaxf(mx0, v0); mx1 = fmaxf(mx1, v1);
            }
        }
        mx0 = fmaxf(mx0, __shfl_xor_sync(0xffffffffu, mx0, 1));
        mx0 = fmaxf(mx0, __shfl_xor_sync(0xffffffffu, mx0, 2));
        mx1 = fmaxf(mx1, __shfl_xor_sync(0xffffffffu, mx1, 1));
        mx1 = fmaxf(mx1, __shfl_xor_sync(0xffffffffu, mx1, 2));
        float m0n = fmaxf(m0, mx0), m1n = fmaxf(m1, mx1);
        float cr0 = __expf(m0 - m0n), cr1 = __expf(m1 - m1n);
        float sum0 = 0.f, sum1 = 0.f;
        #pragma unroll
        for (int nb = 0; nb < 8; nb++) {
            #pragma unroll
            for (int e = 0; e < 2; e++) {
                float p0 = __expf(s[nb][e]   - m0n);
                float p1 = __expf(s[nb][2+e] - m1n);
                s[nb][e] = p0; s[nb][2+e] = p1;
                sum0 += p0; sum1 += p1;
            }
        }
        sum0 += __shfl_xor_sync(0xffffffffu, sum0, 1);
        sum0 += __shfl_xor_sync(0xffffffffu, sum0, 2);
        sum1 += __shfl_xor_sync(0xffffffffu, sum1, 1);
        sum1 += __shfl_xor_sync(0xffffffffu, sum1, 2);
        ls0 = ls0 * cr0 + sum0; m0 = m0n;
        ls1 = ls1 * cr1 + sum1; m1 = m1n;
        #pragma unroll
        for (int i = 0; i < 16; i++) {
            o[i][0] *= cr0; o[i][1] *= cr0;
            o[i][2] *= cr1; o[i][3] *= cr1;
        }

        // ---- P -> split bf16 A-fragments ----
        uint32_t ph[4][4], pl[4][4];
        #pragma unroll
        for (int j2 = 0; j2 < 4; j2++) {
            #pragma unroll
            for (int q = 0; q < 4; q++) {
                int nb = 2 * j2 + (q >> 1);
                int e  = (q & 1) * 2;
                unsigned short ha, la, hb, lb2;
                split_bf16(s[nb][e],     ha, la);
                split_bf16(s[nb][e + 1], hb, lb2);
                int slot = (q >> 1) * 2 + (q & 1);   // 0:a0(nb even,e0) 1:a1(e2) 2:a2 3:a3
                ph[j2][slot] = pack2(ha, hb);
                pl[j2][slot] = pack2(la, lb2);
            }
        }

        // ---- O += Ph Vh + Pl Vh + Ph Vl (V via ldmatrix.trans) ----
        #pragma unroll
        for (int j2 = 0; j2 < 4; j2++) {
            int vrow = j2 * 16 + vrbase;
            uint32_t vroff = sv + vrow * 512;
            uint32_t vr7 = vrow & 7;
            #pragma unroll
            for (int nbp = 0; nbp < 8; nbp++) {
                uint32_t ch = 2 * nbp + vchi;
                uint32_t vhf[4], vlf[4];
                ldsm_x4_t(vhf, vroff + ((ch ^ vr7) & 15u) * 16);
                ldsm_x4_t(vlf, vroff + (16u | ((ch ^ vr7) & 15u)) * 16);
                mma_16816(o[2*nbp],   ph[j2], vhf[0], vhf[1]);
                mma_16816(o[2*nbp+1], ph[j2], vhf[2], vhf[3]);
                mma_16816(o[2*nbp],   pl[j2], vhf[0], vhf[1]);
                mma_16816(o[2*nbp+1], pl[j2], vhf[2], vhf[3]);
                mma_16816(o[2*nbp],   ph[j2], vlf[0], vlf[1]);
                mma_16816(o[2*nbp+1], ph[j2], vlf[2], vlf[3]);
            }
        }

        __syncthreads();
        int nxt = kt + 2;
        if (nxt < ntiles) {
            #pragma unroll
            for (int it = 0; it < 8; it++) {
                int idx = it * 256 + tid;
                int r = idx >> 5, c = idx & 31;
                uint32_t dsw = (uint32_t)(kt & 1) * 65536 + r * 512 + csw(c, r) * 16;
                size_t go = (size_t)(nxt * 64 + r) * 256 + c * 8;
                cp_async16(sbase + dsw,         Kg + go);
                cp_async16(sbase + 32768 + dsw, Vg + go);
            }
        }
        cp_commit();
    }

    // ---- epilogue: write split-bf16 rows of Apack directly ----
    float inv0 = 1.0f / ls0, inv1 = 1.0f / ls1;
    int t0 = b * S_ + qt * 128 + warp * 16 + (lane >> 2);
    size_t r0b = (size_t)t0 * KPRIME;
    size_t r1b = (size_t)(t0 + 8) * KPRIME;
    #pragma unroll
    for (int db = 0; db < 16; db++) {
        int c = h * 128 + db * 8 + colb;
        unsigned short h0, l0, h1, l1;
        split_bf16(o[db][0] * inv0, h0, l0);
        split_bf16(o[db][1] * inv0, h1, l1);
        uint32_t hi = pack2(h0, h1), lo = pack2(l0, l1);
        *(uint32_t*)((__nv_bfloat16*)Apk + r0b + c)        = hi;
        *(uint32_t*)((__nv_bfloat16*)Apk + r0b + 2048 + c) = lo;
        *(uint32_t*)((__nv_bfloat16*)Apk + r0b + 4096 + c) = hi;
        split_bf16(o[db][2] * inv1, h0, l0);
        split_bf16(o[db][3] * inv1, h1, l1);
        hi = pack2(h0, h1); lo = pack2(l0, l1);
        *(uint32_t*)((__nv_bfloat16*)Apk + r1b + c)        = hi;
        *(uint32_t*)((__nv_bfloat16*)Apk + r1b + 2048 + c) = lo;
        *(uint32_t*)((__nv_bfloat16*)Apk + r1b + 4096 + c) = hi;
    }
}

// ---------------- launcher ----------------
extern "C" void kernel_launch(void* const* d_in, const int* in_sizes, int n_in,
                              void* d_out, int out_size)
{
    const float* x       = (const float*)d_in[0];
    const float* cosb    = (const float*)d_in[1];
    const float* sinb    = (const float*)d_in[2];
    const float* mask    = (const float*)d_in[3];
    const float* q_w     = (const float*)d_in[4];
    const float* q_b     = (const float*)d_in[5];
    const float* k_w     = (const float*)d_in[6];
    const float* k_b     = (const float*)d_in[7];
    const float* v_w     = (const float*)d_in[8];
    const float* v_b     = (const float*)d_in[9];
    const float* q_gamma = (const float*)d_in[10];
    const float* k_gamma = (const float*)d_in[11];
    const float* o_w     = (const float*)d_in[12];
    float* out = (float*)d_out;

    float* scratch = nullptr;
    cudaGetSymbolAddress((void**)&scratch, g_scratch);
    float* gqkv = scratch + OFF_GQKV;
    float* geff = scratch + OFF_EFF;
    float* bias = scratch + OFF_BIAS;
    __nv_bfloat16* Apack = (__nv_bfloat16*)(scratch + OFF_APK);
    __nv_bfloat16* Bqkv  = (__nv_bfloat16*)(scratch + OFF_BQKV);
    __nv_bfloat16* Bow   = (__nv_bfloat16*)(scratch + OFF_BOW);
    __nv_bfloat16* Qpk   = (__nv_bfloat16*)(scratch + OFF_QPK);
    __nv_bfloat16* Kpk   = (__nv_bfloat16*)(scratch + OFF_KPK);
    __nv_bfloat16* Vpk   = (__nv_bfloat16*)(scratch + OFF_VPK);

    cudaFuncSetAttribute(gemm_mma_kernel, cudaFuncAttributeMaxDynamicSharedMemorySize, GEMM_SMEM);
    cudaFuncSetAttribute(attn_tc_kernel, cudaFuncAttributeMaxDynamicSharedMemorySize, ATTN_SMEM2);

    eff_kernel<<<B_, 256>>>(mask, geff);
    biascat_kernel<<<10, 256>>>(q_b, k_b, v_b, bias);

    convA_kernel<<<2048, 256>>>(x, Apack);
    convB_kernel<<<dim3(64, 64), 256>>>(q_w, Bqkv, 2048, 0);
    convB_kernel<<<dim3(8, 64),  256>>>(k_w, Bqkv, 256, 2048);
    convB_kernel<<<dim3(8, 64),  256>>>(v_w, Bqkv, 256, 2304);
    convB_kernel<<<dim3(64, 64), 256>>>(o_w, Bow, 2048, 0);

    gemm_mma_kernel<<<dim3(NQKV / 128, 16), 256, GEMM_SMEM>>>(Apack, Bqkv, bias, gqkv, NQKV);

    post_kernel<<<dim3(20, TOK), 128>>>(gqkv, cosb, sinb, mask, q_gamma, k_gamma, Qpk, Kpk, Vpk);

    attn_tc_kernel<<<256, 256, ATTN_SMEM2>>>(Qpk, Kpk, Vpk, geff, Apack);

    gemm_mma_kernel<<<dim3(16, 16), 256, GEMM_SMEM>>>(Apack, Bow, nullptr, out, 2048);
}

// round 6
// speedup vs baseline: 3.7928x; 1.4807x over previous
#include <cuda_runtime.h>
#include <cuda_fp16.h>
#include <math.h>
#include <stdint.h>

#define B_   2
#define S_   1024
#define HID_ 2048
#define NH_  16
#define NKV_ 2
#define HD_  128
#define G_   (NH_/NKV_)
#define TOK  (B_*S_)

#define KPRIME 4096        // 2 * 2048 (fp16 2-term split: [Ah | Al], B indexed k&2047)
#define NQKV   2560

// ---------------- scratch (float offsets, all 16B-aligned) ----------------
#define OFF_GQKV 0              // 2048*2560 f32            = 5242880
#define OFF_EFF  5242880        // 2 (+2 pad)
#define OFF_BIAS 5242884        // 2560
#define OFF_APK  5245444        // 2048*4096 fp16           = 4194304 floats
#define OFF_BQKV 9439748        // 2560*2048 fp16           = 2621440 floats
#define OFF_BOW  12061188       // 2048*2048 fp16           = 2097152 floats
#define OFF_QPK  14158340       // 32768*256 fp16           = 4194304 floats
#define OFF_KPK  18352644       // 4096*128 fp16            = 262144 floats
#define OFF_VPK  18614788       // 262144 floats
#define SCRATCH_F 18876932
__device__ __align__(256) float g_scratch[SCRATCH_F];

// ---------------- helpers ----------------
__device__ __forceinline__ uint32_t smem_u32(const void* p) {
    uint32_t a;
    asm("{ .reg .u64 t; cvta.to.shared.u64 t, %1; cvt.u32.u64 %0, t; }" : "=r"(a) : "l"(p));
    return a;
}
__device__ __forceinline__ void split_h(float f, unsigned short& h, unsigned short& l) {
    __half hh = __float2half_rn(f);
    float r = f - __half2float(hh);
    __half ll = __float2half_rn(r);
    h = __half_as_ushort(hh);
    l = __half_as_ushort(ll);
}
__device__ __forceinline__ uint32_t pack2(unsigned short a, unsigned short b) {
    return (uint32_t)a | ((uint32_t)b << 16);
}
__device__ __forceinline__ void cp_async16(uint32_t saddr, const void* gaddr) {
    asm volatile("cp.async.cg.shared.global [%0], [%1], 16;" :: "r"(saddr), "l"(gaddr));
}
__device__ __forceinline__ void cp_commit() {
    asm volatile("cp.async.commit_group;");
}
template <int N>
__device__ __forceinline__ void cp_wait() {
    asm volatile("cp.async.wait_group %0;" :: "n"(N));
}
__device__ __forceinline__ void ldsm_x4(uint32_t* f, uint32_t addr) {
    asm volatile("ldmatrix.sync.aligned.m8n8.x4.shared.b16 {%0,%1,%2,%3}, [%4];"
                 : "=r"(f[0]), "=r"(f[1]), "=r"(f[2]), "=r"(f[3]) : "r"(addr));
}
__device__ __forceinline__ void ldsm_x4_t(uint32_t* f, uint32_t addr) {
    asm volatile("ldmatrix.sync.aligned.m8n8.x4.trans.shared.b16 {%0,%1,%2,%3}, [%4];"
                 : "=r"(f[0]), "=r"(f[1]), "=r"(f[2]), "=r"(f[3]) : "r"(addr));
}
__device__ __forceinline__ void mma_16816(float* c, const uint32_t* a, uint32_t b0, uint32_t b1) {
    asm volatile(
        "mma.sync.aligned.m16n8k16.row.col.f32.f16.f16.f32 "
        "{%0,%1,%2,%3}, {%4,%5,%6,%7}, {%8,%9}, {%0,%1,%2,%3};"
        : "+f"(c[0]), "+f"(c[1]), "+f"(c[2]), "+f"(c[3])
        : "r"(a[0]), "r"(a[1]), "r"(a[2]), "r"(a[3]), "r"(b0), "r"(b1));
}
// swizzle for 512B rows (32 x 16B chunks, keep bit4)
__device__ __forceinline__ uint32_t csw(uint32_t c, uint32_t row) {
    return (c & 0x10u) | ((c ^ (row & 7u)) & 0x0Fu);
}
// swizzle for 256B rows (16 x 16B chunks, keep bit3)
__device__ __forceinline__ uint32_t csw8(uint32_t c, uint32_t row) {
    return (c & 0x8u) | ((c ^ (row & 7u)) & 0x7u);
}

// ---------------- eff ----------------
__global__ void eff_kernel(const float* __restrict__ mask, float* __restrict__ eff) {
    int b = blockIdx.x;
    float s = 0.f;
    for (int i = threadIdx.x; i < S_; i += blockDim.x) s += mask[b * S_ + i];
    #pragma unroll
    for (int off = 16; off; off >>= 1) s += __shfl_xor_sync(0xffffffffu, s, off);
    __shared__ float red[8];
    if ((threadIdx.x & 31) == 0) red[threadIdx.x >> 5] = s;
    __syncthreads();
    if (threadIdx.x == 0) {
        float t = 0.f;
        for (int i = 0; i < (int)(blockDim.x >> 5); i++) t += red[i];
        eff[b] = t;
    }
}

// ---------------- bias concat ----------------
__global__ void biascat_kernel(const float* __restrict__ qb, const float* __restrict__ kb,
                               const float* __restrict__ vb, float* __restrict__ o) {
    int i = blockIdx.x * 256 + threadIdx.x;
    if (i < 2048) o[i] = qb[i];
    else if (i < 2304) o[i] = kb[i - 2048];
    else if (i < 2560) o[i] = vb[i - 2304];
}

// ---------------- pack activations X[2048x2048] f32 -> [Xh | Xl] fp16 rows of 4096 ----------------
__global__ void __launch_bounds__(256) convA_kernel(const float* __restrict__ X,
                                                    __half* __restrict__ Ap) {
    int g = blockIdx.x * 256 + threadIdx.x;
    int m = g >> 8;
    int kg = (g & 255) << 3;
    const float* xp = X + ((size_t)m << 11) + kg;
    float f[8];
    *(float4*)f       = *(const float4*)xp;
    *(float4*)(f + 4) = *(const float4*)(xp + 4);
    unsigned short h[8], l[8];
    #pragma unroll
    for (int i = 0; i < 8; i++) split_h(f[i], h[i], l[i]);
    uint4 Hi = make_uint4(pack2(h[0],h[1]), pack2(h[2],h[3]), pack2(h[4],h[5]), pack2(h[6],h[7]));
    uint4 Lo = make_uint4(pack2(l[0],l[1]), pack2(l[2],l[3]), pack2(l[4],l[5]), pack2(l[6],l[7]));
    __half* base = Ap + (size_t)m * KPRIME;
    *(uint4*)(base + kg)        = Hi;
    *(uint4*)(base + 2048 + kg) = Lo;
}

// ---------------- pack weights (transposed) W[2048(K) x N] -> rows (noff+n) x 2048 fp16 ----------------
__global__ void __launch_bounds__(256) convB_kernel(const float* __restrict__ W,
                                                    __half* __restrict__ Bp,
                                                    int N, int noff) {
    __shared__ float s[32][33];
    int n0 = blockIdx.x << 5, k0 = blockIdx.y << 5;
    int tid = threadIdx.x;
    #pragma unroll
    for (int p = 0; p < 4; p++) {
        int e = tid + p * 256;
        int ki = e >> 5, ni = e & 31;
        s[ki][ni] = W[(size_t)(k0 + ki) * N + n0 + ni];
    }
    __syncthreads();
    if (tid < 128) {
        int ni = tid >> 2, kg = (tid & 3) << 3;
        unsigned short h[8];
        #pragma unroll
        for (int j = 0; j < 8; j++) h[j] = __half_as_ushort(__float2half_rn(s[kg + j][ni]));
        uint4 Hi = make_uint4(pack2(h[0],h[1]), pack2(h[2],h[3]), pack2(h[4],h[5]), pack2(h[6],h[7]));
        *(uint4*)(Bp + (size_t)(noff + n0 + ni) * 2048 + k0 + kg) = Hi;
    }
}

// ---------------- HMMA fp16 GEMM: C[M,Ntot] = A[M,4096] @ B[(k&2047)]^T (+bias) ----------------
#define BKC 32
#define STAGE_B 16384
#define GEMM_SMEM (4 * STAGE_B)
#define KITERS (KPRIME / BKC)   // 128

__device__ __forceinline__ void stage_load(uint32_t sbase, int stage,
                                           const __half* Ag, const __half* Bg,
                                           int k0, int lrow, int lchunk) {
    uint32_t sa = sbase + stage * STAGE_B;
    int kb = k0 & 2047;
    #pragma unroll
    for (int i = 0; i < 2; i++) {
        int row = lrow + i * 64;
        uint32_t sw = (uint32_t)((lchunk ^ ((row >> 1) & 3)) << 4);
        cp_async16(sa + row * 64 + sw,        Ag + (size_t)row * KPRIME + k0 + lchunk * 8);
        cp_async16(sa + 8192 + row * 64 + sw, Bg + (size_t)row * 2048   + kb + lchunk * 8);
    }
}

__global__ void __launch_bounds__(256, 2) gemm_mma_kernel(
    const __half* __restrict__ A,
    const __half* __restrict__ Bm,
    const float* __restrict__ bias,
    float* __restrict__ C, int Ntot)
{
    extern __shared__ char smc[];
    uint32_t sbase = smem_u32(smc);

    const int tid = threadIdx.x;
    const int mt = blockIdx.y, nt = blockIdx.x;
    const int warp = tid >> 5, lane = tid & 31;
    const int wm = warp >> 2, wn = warp & 3;

    const __half* Ag = A  + (size_t)(mt * 128) * KPRIME;
    const __half* Bg = Bm + (size_t)(nt * 128) * 2048;

    const int lrow = tid >> 2;
    const int lchunk = tid & 3;

    const int arow = wm * 64 + ((lane >> 3) & 1) * 8 + (lane & 7);
    const int achi = (lane >> 4) & 1;
    const uint32_t asw = (uint32_t)((arow >> 1) & 3);
    const uint32_t abase = (uint32_t)(arow * 64);

    const int brow = wn * 32 + ((lane >> 4) & 1) * 8 + (lane & 7);
    const int bclo = (lane >> 3) & 1;
    const uint32_t bsw = (uint32_t)((brow >> 1) & 3);
    const uint32_t bbase = (uint32_t)(brow * 64);

    float acc[16][4];
    #pragma unroll
    for (int i = 0; i < 16; i++)
        #pragma unroll
        for (int j = 0; j < 4; j++) acc[i][j] = 0.f;

    #pragma unroll
    for (int s = 0; s < 3; s++) {
        stage_load(sbase, s, Ag, Bg, s * BKC, lrow, lchunk);
        cp_commit();
    }

    for (int kt = 0; kt < KITERS; kt++) {
        cp_wait<2>();
        __syncthreads();

        int nxt = kt + 3;
        if (nxt < KITERS) stage_load(sbase, nxt & 3, Ag, Bg, nxt * BKC, lrow, lchunk);
        cp_commit();

        uint32_t sa = sbase + (kt & 3) * STAGE_B;
        uint32_t sb = sa + 8192;

        #pragma unroll
        for (int ks = 0; ks < 2; ks++) {
            uint32_t af[4][4];
            #pragma unroll
            for (int m = 0; m < 4; m++)
                ldsm_x4(af[m], sa + abase + m * 1024 + ((((uint32_t)(ks * 2 + achi)) ^ asw) << 4));
            uint32_t bf0[4], bf1[4];
            ldsm_x4(bf0, sb + bbase +        ((((uint32_t)(ks * 2 + bclo)) ^ bsw) << 4));
            ldsm_x4(bf1, sb + bbase + 1024 + ((((uint32_t)(ks * 2 + bclo)) ^ bsw) << 4));
            #pragma unroll
            for (int m = 0; m < 4; m++) {
                mma_16816(acc[m * 4 + 0], af[m], bf0[0], bf0[1]);
                mma_16816(acc[m * 4 + 1], af[m], bf0[2], bf0[3]);
                mma_16816(acc[m * 4 + 2], af[m], bf1[0], bf1[1]);
                mma_16816(acc[m * 4 + 3], af[m], bf1[2], bf1[3]);
            }
        }
    }

    #pragma unroll
    for (int n = 0; n < 4; n++) {
        int col = nt * 128 + wn * 32 + n * 8 + (lane & 3) * 2;
        float b0 = bias ? bias[col]     : 0.f;
        float b1 = bias ? bias[col + 1] : 0.f;
        #pragma unroll
        for (int m = 0; m < 4; m++) {
            int row = mt * 128 + wm * 64 + m * 16 + (lane >> 2);
            float2 v0 = make_float2(acc[m * 4 + n][0] + b0, acc[m * 4 + n][1] + b1);
            float2 v1 = make_float2(acc[m * 4 + n][2] + b0, acc[m * 4 + n][3] + b1);
            *(float2*)(C + (size_t)row * Ntot + col)       = v0;
            *(float2*)(C + (size_t)(row + 8) * Ntot + col) = v1;
        }
    }
}

// ---------------- RMSNorm + RoPE + mask -> Q split fp16 (256), K/V plain fp16 (128) ----------------
__global__ void post_kernel(
    const float* __restrict__ gqkv,
    const float* __restrict__ cosb, const float* __restrict__ sinb,
    const float* __restrict__ mask,
    const float* __restrict__ q_gamma, const float* __restrict__ k_gamma,
    __half* __restrict__ Qpk, __half* __restrict__ Kpk, __half* __restrict__ Vpk)
{
    int unit = blockIdx.x;
    int t = blockIdx.y;
    int b = t >> 10, s = t & (S_ - 1);
    int d = threadIdx.x;
    float mval = mask[t];
    const float* rowp = gqkv + (size_t)t * NQKV;

    if (unit >= 18) {
        int kh = unit - 18;
        float v = rowp[2304 + kh * HD_ + d] * mval;
        Vpk[((size_t)(b * NKV_ + kh) * S_ + s) * 128 + d] = __float2half_rn(v);
        return;
    }

    float val;
    const float* gamma;
    if (unit < 16) { val = rowp[unit * HD_ + d]; gamma = q_gamma; }
    else           { val = rowp[2048 + (unit - 16) * HD_ + d]; gamma = k_gamma; }

    float v2 = val * val;
    #pragma unroll
    for (int off = 16; off; off >>= 1) v2 += __shfl_xor_sync(0xffffffffu, v2, off);
    __shared__ float red[4];
    __shared__ float sh[128];
    if ((d & 31) == 0) red[d >> 5] = v2;
    __syncthreads();
    float tot = red[0] + red[1] + red[2] + red[3];
    float nv = gamma[d] * val * rsqrtf(tot * (1.0f / HD_) + 1e-6f);
    sh[d] = nv;
    __syncthreads();
    float partner = (d < 64) ? -sh[d + 64] : sh[d - 64];

    int sec = (d < 16) ? 0 : (d < 40) ? 1 : (d < 64) ? 2 : (d < 80) ? 0 : (d < 104) ? 1 : 2;
    size_t ci = (((size_t)sec * B_ + b) * S_ + s) * HD_ + d;
    float o = nv * cosb[ci] + partner * sinb[ci];

    if (unit < 16) {
        unsigned short hi, lo;
        split_h(o, hi, lo);
        __half* qp = Qpk + ((size_t)(b * NH_ + unit) * S_ + s) * 256;
        qp[d]       = __ushort_as_half(hi);
        qp[128 + d] = __ushort_as_half(lo);
    } else {
        Kpk[((size_t)(b * NKV_ + (unit - 16)) * S_ + s) * 128 + d] = __float2half_rn(o * mval);
    }
}

// ---------------- tensor-core flash attention (fp16) ----------------
// CTA = 64 q-rows (4 warps x 16), 128 threads, 2 CTAs/SM.
// smem: Q stage 32KB + 2 x (K 16KB + V 16KB) = 96KB.
#define ATTN_SMEM 98304

__global__ void __launch_bounds__(128, 2) attn_tc_kernel(
    const __half* __restrict__ Qpk, const __half* __restrict__ Kpk,
    const __half* __restrict__ Vpk, const float* __restrict__ eff,
    __half* __restrict__ Apk)
{
    extern __shared__ char smc[];
    uint32_t sbase = smem_u32(smc);

    int bid = blockIdx.x;
    int qt = 15 - (bid >> 5);           // descending q-tile (64 rows)
    int rem = bid & 31;
    int h = rem >> 1, b = rem & 1;
    int kvh = h / G_;
    int tid = threadIdx.x, warp = tid >> 5, lane = tid & 31;

    const __half* Qg = Qpk + ((size_t)(b * NH_ + h) * S_ + qt * 64) * 256;
    const __half* Kg = Kpk + ((size_t)(b * NKV_ + kvh) * S_) * 128;
    const __half* Vg = Vpk + ((size_t)(b * NKV_ + kvh) * S_) * 128;

    // ---- stage Q (64 rows x 512B) ----
    #pragma unroll
    for (int it = 0; it < 16; it++) {
        int idx = it * 128 + tid;
        int r = idx >> 5, c = idx & 31;
        cp_async16(sbase + r * 512 + csw(c, r) * 16, Qg + (size_t)r * 256 + c * 8);
    }
    cp_commit();
    cp_wait<0>();
    __syncthreads();

    // ---- extract Q fragments ----
    uint32_t qh[8][4], ql[8][4];
    {
        int row = warp * 16 + ((lane >> 3) & 1) * 8 + (lane & 7);
        uint32_t roff = sbase + row * 512;
        uint32_t r7 = row & 7;
        int chi = (lane >> 4) & 1;
        #pragma unroll
        for (int j = 0; j < 8; j++) {
            uint32_t ch = 2 * j + chi;
            ldsm_x4(qh[j], roff + ((ch ^ r7) & 15u) * 16);
            ldsm_x4(ql[j], roff + (16u | ((ch ^ r7) & 15u)) * 16);
        }
    }

    int ntiles = qt + 1;
    int eff_i = (int)(eff[b] + 0.5f);

    // ---- prologue: KV tiles 0,1 ----
    #pragma unroll
    for (int pt = 0; pt < 2; pt++) {
        if (pt < ntiles) {
            #pragma unroll
            for (int it = 0; it < 8; it++) {
                int idx = it * 128 + tid;
                int r = idx >> 4, c = idx & 15;
                uint32_t ds = 32768u + (uint32_t)pt * 32768 + r * 256 + csw8(c, r) * 16;
                size_t go = (size_t)(pt * 64 + r) * 128 + c * 8;
                cp_async16(sbase + ds,         Kg + go);
                cp_async16(sbase + ds + 16384, Vg + go);
            }
        }
        cp_commit();
    }

    float m0 = -1e30f, m1 = -1e30f, ls0 = 0.f, ls1 = 0.f;
    float o[16][4];
    #pragma unroll
    for (int i = 0; i < 16; i++) { o[i][0] = o[i][1] = o[i][2] = o[i][3] = 0.f; }

    const float scale = 0.08838834764831845f;
    int row0 = qt * 64 + warp * 16 + (lane >> 2);
    int colb = (lane & 3) * 2;
    int krbase = ((lane >> 4) & 1) * 8 + (lane & 7);
    int kchi = (lane >> 3) & 1;
    int vrbase = ((lane >> 3) & 1) * 8 + (lane & 7);
    int vchi = (lane >> 4) & 1;

    for (int kt = 0; kt < ntiles; kt++) {
        cp_wait<1>();
        __syncthreads();
        uint32_t sk = sbase + 32768u + (uint32_t)(kt & 1) * 32768;
        uint32_t sv = sk + 16384;

        // ---- S = (Qh + Ql) K ----
        float s[8][4];
        #pragma unroll
        for (int i = 0; i < 8; i++) { s[i][0] = s[i][1] = s[i][2] = s[i][3] = 0.f; }

        #pragma unroll
        for (int nbp = 0; nbp < 4; nbp++) {
            int krow = nbp * 16 + krbase;
            uint32_t kroff = sk + krow * 256;
            uint32_t kr7 = krow & 7;
            #pragma unroll
            for (int j = 0; j < 8; j++) {
                uint32_t ch = 2 * j + kchi;
                uint32_t kf[4];
                ldsm_x4(kf, kroff + ((ch & 8u) | ((ch ^ kr7) & 7u)) * 16);
                mma_16816(s[2*nbp],   qh[j], kf[0], kf[1]);
                mma_16816(s[2*nbp+1], qh[j], kf[2], kf[3]);
                mma_16816(s[2*nbp],   ql[j], kf[0], kf[1]);
                mma_16816(s[2*nbp+1], ql[j], kf[2], kf[3]);
            }
        }

        // ---- mask + online softmax ----
        float mx0 = -1e30f, mx1 = -1e30f;
        #pragma unroll
        for (int nb = 0; nb < 8; nb++) {
            int c0 = kt * 64 + nb * 8 + colb;
            #pragma unroll
            for (int e = 0; e < 2; e++) {
                int cc = c0 + e;
                float v0 = (cc <= row0     && cc < eff_i) ? s[nb][e]   * scale : -1e9f;
                float v1 = (cc <= row0 + 8 && cc < eff_i) ? s[nb][2+e] * scale : -1e9f;
                s[nb][e] = v0; s[nb][2+e] = v1;
                mx0 = fmaxf(mx0, v0); mx1 = fmaxf(mx1, v1);
            }
        }
        mx0 = fmaxf(mx0, __shfl_xor_sync(0xffffffffu, mx0, 1));
        mx0 = fmaxf(mx0, __shfl_xor_sync(0xffffffffu, mx0, 2));
        mx1 = fmaxf(mx1, __shfl_xor_sync(0xffffffffu, mx1, 1));
        mx1 = fmaxf(mx1, __shfl_xor_sync(0xffffffffu, mx1, 2));
        float m0n = fmaxf(m0, mx0), m1n = fmaxf(m1, mx1);
        float cr0 = __expf(m0 - m0n), cr1 = __expf(m1 - m1n);
        float sum0 = 0.f, sum1 = 0.f;
        #pragma unroll
        for (int nb = 0; nb < 8; nb++) {
            #pragma unroll
            for (int e = 0; e < 2; e++) {
                float p0 = __expf(s[nb][e]   - m0n);
                float p1 = __expf(s[nb][2+e] - m1n);
                s[nb][e] = p0; s[nb][2+e] = p1;
                sum0 += p0; sum1 += p1;
            }
        }
        sum0 += __shfl_xor_sync(0xffffffffu, sum0, 1);
        sum0 += __shfl_xor_sync(0xffffffffu, sum0, 2);
        sum1 += __shfl_xor_sync(0xffffffffu, sum1, 1);
        sum1 += __shfl_xor_sync(0xffffffffu, sum1, 2);
        ls0 = ls0 * cr0 + sum0; m0 = m0n;
        ls1 = ls1 * cr1 + sum1; m1 = m1n;
        #pragma unroll
        for (int i = 0; i < 16; i++) {
            o[i][0] *= cr0; o[i][1] *= cr0;
            o[i][2] *= cr1; o[i][3] *= cr1;
        }

        // ---- P -> split fp16 A-fragments ----
        uint32_t ph[4][4], pl[4][4];
        #pragma unroll
        for (int j2 = 0; j2 < 4; j2++) {
            #pragma unroll
            for (int q = 0; q < 4; q++) {
                int nb = 2 * j2 + (q >> 1);
                int e  = (q & 1) * 2;
                unsigned short ha, la, hb, lb2;
                split_h(s[nb][e],     ha, la);
                split_h(s[nb][e + 1], hb, lb2);
                int slot = (q >> 1) * 2 + (q & 1);
                ph[j2][slot] = pack2(ha, hb);
                pl[j2][slot] = pack2(la, lb2);
            }
        }

        // ---- O += (Ph + Pl) V ----
        #pragma unroll
        for (int j2 = 0; j2 < 4; j2++) {
            int vrow = j2 * 16 + vrbase;
            uint32_t vroff = sv + vrow * 256;
            uint32_t vr7 = vrow & 7;
            #pragma unroll
            for (int nbp = 0; nbp < 8; nbp++) {
                uint32_t ch = 2 * nbp + vchi;
                uint32_t vf[4];
                ldsm_x4_t(vf, vroff + ((ch & 8u) | ((ch ^ vr7) & 7u)) * 16);
                mma_16816(o[2*nbp],   ph[j2], vf[0], vf[1]);
                mma_16816(o[2*nbp+1], ph[j2], vf[2], vf[3]);
                mma_16816(o[2*nbp],   pl[j2], vf[0], vf[1]);
                mma_16816(o[2*nbp+1], pl[j2], vf[2], vf[3]);
            }
        }

        __syncthreads();
        int nxt = kt + 2;
        if (nxt < ntiles) {
            #pragma unroll
            for (int it = 0; it < 8; it++) {
                int idx = it * 128 + tid;
                int r = idx >> 4, c = idx & 15;
                uint32_t ds = 32768u + (uint32_t)(kt & 1) * 32768 + r * 256 + csw8(c, r) * 16;
                size_t go = (size_t)(nxt * 64 + r) * 128 + c * 8;
                cp_async16(sbase + ds,         Kg + go);
                cp_async16(sbase + ds + 16384, Vg + go);
            }
        }
        cp_commit();
    }

    // ---- epilogue: write split fp16 rows of Apack ----
    float inv0 = 1.0f / ls0, inv1 = 1.0f / ls1;
    int t0 = b * S_ + qt * 64 + warp * 16 + (lane >> 2);
    size_t r0b = (size_t)t0 * KPRIME;
    size_t r1b = (size_t)(t0 + 8) * KPRIME;
    #pragma unroll
    for (int db = 0; db < 16; db++) {
        int c = h * 128 + db * 8 + colb;
        unsigned short h0, l0, h1, l1;
        split_h(o[db][0] * inv0, h0, l0);
        split_h(o[db][1] * inv0, h1, l1);
        *(uint32_t*)(Apk + r0b + c)        = pack2(h0, h1);
        *(uint32_t*)(Apk + r0b + 2048 + c) = pack2(l0, l1);
        split_h(o[db][2] * inv1, h0, l0);
        split_h(o[db][3] * inv1, h1, l1);
        *(uint32_t*)(Apk + r1b + c)        = pack2(h0, h1);
        *(uint32_t*)(Apk + r1b + 2048 + c) = pack2(l0, l1);
    }
}

// ---------------- launcher ----------------
extern "C" void kernel_launch(void* const* d_in, const int* in_sizes, int n_in,
                              void* d_out, int out_size)
{
    const float* x       = (const float*)d_in[0];
    const float* cosb    = (const float*)d_in[1];
    const float* sinb    = (const float*)d_in[2];
    const float* mask    = (const float*)d_in[3];
    const float* q_w     = (const float*)d_in[4];
    const float* q_b     = (const float*)d_in[5];
    const float* k_w     = (const float*)d_in[6];
    const float* k_b     = (const float*)d_in[7];
    const float* v_w     = (const float*)d_in[8];
    const float* v_b     = (const float*)d_in[9];
    const float* q_gamma = (const float*)d_in[10];
    const float* k_gamma = (const float*)d_in[11];
    const float* o_w     = (const float*)d_in[12];
    float* out = (float*)d_out;

    float* scratch = nullptr;
    cudaGetSymbolAddress((void**)&scratch, g_scratch);
    float* gqkv = scratch + OFF_GQKV;
    float* geff = scratch + OFF_EFF;
    float* bias = scratch + OFF_BIAS;
    __half* Apack = (__half*)(scratch + OFF_APK);
    __half* Bqkv  = (__half*)(scratch + OFF_BQKV);
    __half* Bow   = (__half*)(scratch + OFF_BOW);
    __half* Qpk   = (__half*)(scratch + OFF_QPK);
    __half* Kpk   = (__half*)(scratch + OFF_KPK);
    __half* Vpk   = (__half*)(scratch + OFF_VPK);

    cudaFuncSetAttribute(gemm_mma_kernel, cudaFuncAttributeMaxDynamicSharedMemorySize, GEMM_SMEM);
    cudaFuncSetAttribute(attn_tc_kernel, cudaFuncAttributeMaxDynamicSharedMemorySize, ATTN_SMEM);

    eff_kernel<<<B_, 256>>>(mask, geff);
    biascat_kernel<<<10, 256>>>(q_b, k_b, v_b, bias);

    convA_kernel<<<2048, 256>>>(x, Apack);
    convB_kernel<<<dim3(64, 64), 256>>>(q_w, Bqkv, 2048, 0);
    convB_kernel<<<dim3(8, 64),  256>>>(k_w, Bqkv, 256, 2048);
    convB_kernel<<<dim3(8, 64),  256>>>(v_w, Bqkv, 256, 2304);
    convB_kernel<<<dim3(64, 64), 256>>>(o_w, Bow, 2048, 0);

    gemm_mma_kernel<<<dim3(NQKV / 128, 16), 256, GEMM_SMEM>>>(Apack, Bqkv, bias, gqkv, NQKV);

    post_kernel<<<dim3(20, TOK), 128>>>(gqkv, cosb, sinb, mask, q_gamma, k_gamma, Qpk, Kpk, Vpk);

    attn_tc_kernel<<<512, 128, ATTN_SMEM>>>(Qpk, Kpk, Vpk, geff, Apack);

    gemm_mma_kernel<<<dim3(16, 16), 256, GEMM_SMEM>>>(Apack, Bow, nullptr, out, 2048);
}

// round 7
// speedup vs baseline: 3.9508x; 1.0416x over previous
#include <cuda_runtime.h>
#include <cuda_fp16.h>
#include <math.h>
#include <stdint.h>

#define B_   2
#define S_   1024
#define HID_ 2048
#define NH_  16
#define NKV_ 2
#define HD_  128
#define G_   (NH_/NKV_)
#define TOK  (B_*S_)

#define KPRIME 4096        // fp16 2-term split on A side: [Ah | Al]; B indexed k&2047
#define NQKV   2560

// ---------------- scratch (float offsets, 16B-aligned) ----------------
#define OFF_EFF  0              // 2 (+2 pad)
#define OFF_BIAS 4              // 2560
#define OFF_APK  2564           // 2048*4096 fp16 = 4194304 floats
#define OFF_BQKV 4196868        // 2560*2048 fp16 = 2621440 floats
#define OFF_BOW  6818308        // 2048*2048 fp16 = 2097152 floats
#define OFF_QPK  8915460        // 32768*256 fp16 = 4194304 floats
#define OFF_KPK  13109764       // 4096*128 fp16  = 262144 floats
#define OFF_VPK  13371908       // 262144 floats
#define SCRATCH_F 13634052
__device__ __align__(256) float g_scratch[SCRATCH_F];

// ---------------- helpers ----------------
__device__ __forceinline__ uint32_t smem_u32(const void* p) {
    uint32_t a;
    asm("{ .reg .u64 t; cvta.to.shared.u64 t, %1; cvt.u32.u64 %0, t; }" : "=r"(a) : "l"(p));
    return a;
}
__device__ __forceinline__ void split_h(float f, unsigned short& h, unsigned short& l) {
    __half hh = __float2half_rn(f);
    float r = f - __half2float(hh);
    __half ll = __float2half_rn(r);
    h = __half_as_ushort(hh);
    l = __half_as_ushort(ll);
}
__device__ __forceinline__ uint32_t pack2(unsigned short a, unsigned short b) {
    return (uint32_t)a | ((uint32_t)b << 16);
}
__device__ __forceinline__ void cp_async16(uint32_t saddr, const void* gaddr) {
    asm volatile("cp.async.cg.shared.global [%0], [%1], 16;" :: "r"(saddr), "l"(gaddr));
}
__device__ __forceinline__ void cp_commit() {
    asm volatile("cp.async.commit_group;");
}
template <int N>
__device__ __forceinline__ void cp_wait() {
    asm volatile("cp.async.wait_group %0;" :: "n"(N));
}
__device__ __forceinline__ void ldsm_x4(uint32_t* f, uint32_t addr) {
    asm volatile("ldmatrix.sync.aligned.m8n8.x4.shared.b16 {%0,%1,%2,%3}, [%4];"
                 : "=r"(f[0]), "=r"(f[1]), "=r"(f[2]), "=r"(f[3]) : "r"(addr));
}
__device__ __forceinline__ void ldsm_x4_t(uint32_t* f, uint32_t addr) {
    asm volatile("ldmatrix.sync.aligned.m8n8.x4.trans.shared.b16 {%0,%1,%2,%3}, [%4];"
                 : "=r"(f[0]), "=r"(f[1]), "=r"(f[2]), "=r"(f[3]) : "r"(addr));
}
__device__ __forceinline__ void mma_16816(float* c, const uint32_t* a, uint32_t b0, uint32_t b1) {
    asm volatile(
        "mma.sync.aligned.m16n8k16.row.col.f32.f16.f16.f32 "
        "{%0,%1,%2,%3}, {%4,%5,%6,%7}, {%8,%9}, {%0,%1,%2,%3};"
        : "+f"(c[0]), "+f"(c[1]), "+f"(c[2]), "+f"(c[3])
        : "r"(a[0]), "r"(a[1]), "r"(a[2]), "r"(a[3]), "r"(b0), "r"(b1));
}
__device__ __forceinline__ uint32_t csw(uint32_t c, uint32_t row) {   // 512B rows
    return (c & 0x10u) | ((c ^ (row & 7u)) & 0x0Fu);
}
__device__ __forceinline__ uint32_t csw8(uint32_t c, uint32_t row) {  // 256B rows
    return (c & 0x8u) | ((c ^ (row & 7u)) & 0x7u);
}

// ---------------- eff ----------------
__global__ void eff_kernel(const float* __restrict__ mask, float* __restrict__ eff) {
    int b = blockIdx.x;
    float s = 0.f;
    for (int i = threadIdx.x; i < S_; i += blockDim.x) s += mask[b * S_ + i];
    #pragma unroll
    for (int off = 16; off; off >>= 1) s += __shfl_xor_sync(0xffffffffu, s, off);
    __shared__ float red[8];
    if ((threadIdx.x & 31) == 0) red[threadIdx.x >> 5] = s;
    __syncthreads();
    if (threadIdx.x == 0) {
        float t = 0.f;
        for (int i = 0; i < (int)(blockDim.x >> 5); i++) t += red[i];
        eff[b] = t;
    }
}

// ---------------- bias concat ----------------
__global__ void biascat_kernel(const float* __restrict__ qb, const float* __restrict__ kb,
                               const float* __restrict__ vb, float* __restrict__ o) {
    int i = blockIdx.x * 256 + threadIdx.x;
    if (i < 2048) o[i] = qb[i];
    else if (i < 2304) o[i] = kb[i - 2048];
    else if (i < 2560) o[i] = vb[i - 2304];
}

// ---------------- pack activations X[2048x2048] f32 -> [Xh | Xl] fp16 rows of 4096 ----------------
__global__ void __launch_bounds__(256) convA_kernel(const float* __restrict__ X,
                                                    __half* __restrict__ Ap) {
    int g = blockIdx.x * 256 + threadIdx.x;
    int m = g >> 8;
    int kg = (g & 255) << 3;
    const float* xp = X + ((size_t)m << 11) + kg;
    float f[8];
    *(float4*)f       = *(const float4*)xp;
    *(float4*)(f + 4) = *(const float4*)(xp + 4);
    unsigned short h[8], l[8];
    #pragma unroll
    for (int i = 0; i < 8; i++) split_h(f[i], h[i], l[i]);
    uint4 Hi = make_uint4(pack2(h[0],h[1]), pack2(h[2],h[3]), pack2(h[4],h[5]), pack2(h[6],h[7]));
    uint4 Lo = make_uint4(pack2(l[0],l[1]), pack2(l[2],l[3]), pack2(l[4],l[5]), pack2(l[6],l[7]));
    __half* base = Ap + (size_t)m * KPRIME;
    *(uint4*)(base + kg)        = Hi;
    *(uint4*)(base + 2048 + kg) = Lo;
}

// ---------------- pack weights (transposed) W[2048(K) x N] -> rows (noff+n) x 2048 fp16 ----------------
__global__ void __launch_bounds__(256) convB_kernel(const float* __restrict__ W,
                                                    __half* __restrict__ Bp,
                                                    int N, int noff) {
    __shared__ float s[32][33];
    int n0 = blockIdx.x << 5, k0 = blockIdx.y << 5;
    int tid = threadIdx.x;
    #pragma unroll
    for (int p = 0; p < 4; p++) {
        int e = tid + p * 256;
        int ki = e >> 5, ni = e & 31;
        s[ki][ni] = W[(size_t)(k0 + ki) * N + n0 + ni];
    }
    __syncthreads();
    if (tid < 128) {
        int ni = tid >> 2, kg = (tid & 3) << 3;
        unsigned short h[8];
        #pragma unroll
        for (int j = 0; j < 8; j++) h[j] = __half_as_ushort(__float2half_rn(s[kg + j][ni]));
        uint4 Hi = make_uint4(pack2(h[0],h[1]), pack2(h[2],h[3]), pack2(h[4],h[5]), pack2(h[6],h[7]));
        *(uint4*)(Bp + (size_t)(noff + n0 + ni) * 2048 + k0 + kg) = Hi;
    }
}

// ---------------- shared GEMM mainloop pieces ----------------
#define BKC 32
#define STAGE_B 16384
#define GEMM_SMEM 65536
#define KITERS (KPRIME / BKC)   // 128

__device__ __forceinline__ void stage_load(uint32_t sbase, int stage,
                                           const __half* Ag, const __half* Bg,
                                           int k0, int lrow, int lchunk) {
    uint32_t sa = sbase + stage * STAGE_B;
    int kb = k0 & 2047;
    #pragma unroll
    for (int i = 0; i < 2; i++) {
        int row = lrow + i * 64;
        uint32_t sw = (uint32_t)((lchunk ^ ((row >> 1) & 3)) << 4);
        cp_async16(sa + row * 64 + sw,        Ag + (size_t)row * KPRIME + k0 + lchunk * 8);
        cp_async16(sa + 8192 + row * 64 + sw, Bg + (size_t)row * 2048   + kb + lchunk * 8);
    }
}

// mainloop: fills acc[16][4]; uses the standard 8-warp 2x4 layout.
#define GEMM_MAINLOOP(ACC)                                                            \
    {                                                                                 \
        _Pragma("unroll")                                                             \
        for (int s = 0; s < 3; s++) { stage_load(sbase, s, Ag, Bg, s * BKC, lrow, lchunk); cp_commit(); } \
        for (int kt = 0; kt < KITERS; kt++) {                                         \
            cp_wait<2>();                                                             \
            __syncthreads();                                                          \
            int nxt = kt + 3;                                                         \
            if (nxt < KITERS) stage_load(sbase, nxt & 3, Ag, Bg, nxt * BKC, lrow, lchunk); \
            cp_commit();                                                              \
            uint32_t sa = sbase + (kt & 3) * STAGE_B;                                 \
            uint32_t sb = sa + 8192;                                                  \
            _Pragma("unroll")                                                         \
            for (int ks = 0; ks < 2; ks++) {                                          \
                uint32_t af[4][4];                                                    \
                _Pragma("unroll")                                                     \
                for (int m = 0; m < 4; m++)                                           \
                    ldsm_x4(af[m], sa + abase + m * 1024 + ((((uint32_t)(ks * 2 + achi)) ^ asw) << 4)); \
                uint32_t bf0[4], bf1[4];                                              \
                ldsm_x4(bf0, sb + bbase +        ((((uint32_t)(ks * 2 + bclo)) ^ bsw) << 4)); \
                ldsm_x4(bf1, sb + bbase + 1024 + ((((uint32_t)(ks * 2 + bclo)) ^ bsw) << 4)); \
                _Pragma("unroll")                                                     \
                for (int m = 0; m < 4; m++) {                                         \
                    mma_16816(ACC[m * 4 + 0], af[m], bf0[0], bf0[1]);                 \
                    mma_16816(ACC[m * 4 + 1], af[m], bf0[2], bf0[3]);                 \
                    mma_16816(ACC[m * 4 + 2], af[m], bf1[0], bf1[1]);                 \
                    mma_16816(ACC[m * 4 + 3], af[m], bf1[2], bf1[3]);                 \
                }                                                                     \
            }                                                                         \
        }                                                                             \
    }

#define GEMM_PREAMBLE()                                                               \
    extern __shared__ char smc[];                                                     \
    uint32_t sbase = smem_u32(smc);                                                   \
    const int tid = threadIdx.x;                                                      \
    const int mt = blockIdx.y, nt = blockIdx.x;                                       \
    const int warp = tid >> 5, lane = tid & 31;                                       \
    const int wm = warp >> 2, wn = warp & 3;                                          \
    const int lrow = tid >> 2;                                                        \
    const int lchunk = tid & 3;                                                       \
    const int arow = wm * 64 + ((lane >> 3) & 1) * 8 + (lane & 7);                    \
    const int achi = (lane >> 4) & 1;                                                 \
    const uint32_t asw = (uint32_t)((arow >> 1) & 3);                                 \
    const uint32_t abase = (uint32_t)(arow * 64);                                     \
    const int brow = wn * 32 + ((lane >> 4) & 1) * 8 + (lane & 7);                    \
    const int bclo = (lane >> 3) & 1;                                                 \
    const uint32_t bsw = (uint32_t)((brow >> 1) & 3);                                 \
    const uint32_t bbase = (uint32_t)(brow * 64);                                     \
    float acc[16][4];                                                                 \
    _Pragma("unroll")                                                                 \
    for (int i = 0; i < 16; i++) { acc[i][0]=0.f; acc[i][1]=0.f; acc[i][2]=0.f; acc[i][3]=0.f; }

// ---------------- generic GEMM (O-projection): f32 output ----------------
__global__ void __launch_bounds__(256, 2) gemm_mma_kernel(
    const __half* __restrict__ A, const __half* __restrict__ Bm,
    float* __restrict__ C, int Ntot)
{
    GEMM_PREAMBLE();
    const __half* Ag = A  + (size_t)(mt * 128) * KPRIME;
    const __half* Bg = Bm + (size_t)(nt * 128) * 2048;
    GEMM_MAINLOOP(acc);

    #pragma unroll
    for (int n = 0; n < 4; n++) {
        int col = nt * 128 + wn * 32 + n * 8 + (lane & 3) * 2;
        #pragma unroll
        for (int m = 0; m < 4; m++) {
            int row = mt * 128 + wm * 64 + m * 16 + (lane >> 2);
            *(float2*)(C + (size_t)row * Ntot + col)       = make_float2(acc[m*4+n][0], acc[m*4+n][1]);
            *(float2*)(C + (size_t)(row + 8) * Ntot + col) = make_float2(acc[m*4+n][2], acc[m*4+n][3]);
        }
    }
}

// ---------------- fused QKV GEMM: epilogue does bias + RMSNorm + RoPE + mask + pack ----------------
__global__ void __launch_bounds__(256, 2) gemm_qkv_fused(
    const __half* __restrict__ A, const __half* __restrict__ Bm,
    const float* __restrict__ bias,
    const float* __restrict__ cosb, const float* __restrict__ sinb,
    const float* __restrict__ mask,
    const float* __restrict__ q_gamma, const float* __restrict__ k_gamma,
    __half* __restrict__ Qpk, __half* __restrict__ Kpk, __half* __restrict__ Vpk)
{
    __shared__ float ssq[4][128];
    GEMM_PREAMBLE();
    const __half* Ag = A  + (size_t)(mt * 128) * KPRIME;
    const __half* Bg = Bm + (size_t)(nt * 128) * 2048;
    GEMM_MAINLOOP(acc);

    cp_wait<0>();
    __syncthreads();   // pipeline smem now reusable

    // bias add in place
    #pragma unroll
    for (int n = 0; n < 4; n++) {
        int col = wn * 32 + n * 8 + (lane & 3) * 2;
        float b0 = bias[nt * 128 + col];
        float b1 = bias[nt * 128 + col + 1];
        #pragma unroll
        for (int m = 0; m < 4; m++) {
            acc[m*4+n][0] += b0; acc[m*4+n][1] += b1;
            acc[m*4+n][2] += b0; acc[m*4+n][3] += b1;
        }
    }

    if (nt >= 18) {
        // ---- V: mask-mul, plain fp16 ----
        int kh = nt - 18;
        #pragma unroll
        for (int m = 0; m < 4; m++) {
            int r0 = wm * 64 + m * 16 + (lane >> 2);
            int t0 = mt * 128 + r0;
            int b0g = t0 >> 10, s0g = t0 & 1023;
            float mv0 = mask[t0], mv1 = mask[t0 + 8];
            __half* vp0 = Vpk + ((size_t)(b0g * NKV_ + kh) * S_ + s0g) * 128;
            __half* vp1 = Vpk + ((size_t)(b0g * NKV_ + kh) * S_ + s0g + 8) * 128;
            #pragma unroll
            for (int n = 0; n < 4; n++) {
                int col = wn * 32 + n * 8 + (lane & 3) * 2;
                *(__half2*)(vp0 + col) = __floats2half2_rn(acc[m*4+n][0] * mv0, acc[m*4+n][1] * mv0);
                *(__half2*)(vp1 + col) = __floats2half2_rn(acc[m*4+n][2] * mv1, acc[m*4+n][3] * mv1);
            }
        }
        return;
    }

    // ---- Q or K: RMSNorm over the 128 head dims (== this CTA's N tile) ----
    const bool isQ = (nt < 16);
    const float* gamma = isQ ? q_gamma : k_gamma;
    float* snv = (float*)smc;   // [128 rows][128 cols], col rotated by 4*row

    // per-row sum of squares: quad reduce then cross-warp (wn) via smem
    float ssr0[4], ssr1[4];
    #pragma unroll
    for (int m = 0; m < 4; m++) {
        float a0 = 0.f, a1 = 0.f;
        #pragma unroll
        for (int n = 0; n < 4; n++) {
            a0 += acc[m*4+n][0]*acc[m*4+n][0] + acc[m*4+n][1]*acc[m*4+n][1];
            a1 += acc[m*4+n][2]*acc[m*4+n][2] + acc[m*4+n][3]*acc[m*4+n][3];
        }
        a0 += __shfl_xor_sync(0xffffffffu, a0, 1);
        a0 += __shfl_xor_sync(0xffffffffu, a0, 2);
        a1 += __shfl_xor_sync(0xffffffffu, a1, 1);
        a1 += __shfl_xor_sync(0xffffffffu, a1, 2);
        ssr0[m] = a0; ssr1[m] = a1;
        if ((lane & 3) == 0) {
            int r0 = wm * 64 + m * 16 + (lane >> 2);
            ssq[wn][r0]     = a0;
            ssq[wn][r0 + 8] = a1;
        }
    }
    __syncthreads();

    // normalized values -> rotated smem
    #pragma unroll
    for (int m = 0; m < 4; m++) {
        int r0 = wm * 64 + m * 16 + (lane >> 2);
        int r1 = r0 + 8;
        float tot0 = ssq[0][r0] + ssq[1][r0] + ssq[2][r0] + ssq[3][r0];
        float tot1 = ssq[0][r1] + ssq[1][r1] + ssq[2][r1] + ssq[3][r1];
        float rms0 = rsqrtf(tot0 * (1.0f / HD_) + 1e-6f);
        float rms1 = rsqrtf(tot1 * (1.0f / HD_) + 1e-6f);
        #pragma unroll
        for (int n = 0; n < 4; n++) {
            int d0 = wn * 32 + n * 8 + (lane & 3) * 2;
            float g0 = gamma[d0], g1 = gamma[d0 + 1];
            snv[r0 * 128 + ((d0     + 4 * r0) & 127)] = acc[m*4+n][0] * rms0 * g0;
            snv[r0 * 128 + ((d0 + 1 + 4 * r0) & 127)] = acc[m*4+n][1] * rms0 * g1;
            snv[r1 * 128 + ((d0     + 4 * r1) & 127)] = acc[m*4+n][2] * rms1 * g0;
            snv[r1 * 128 + ((d0 + 1 + 4 * r1) & 127)] = acc[m*4+n][3] * rms1 * g1;
        }
    }
    __syncthreads();

    // RoPE + pack + write. warp handles rows warp*16..+15, lane handles 4 dims.
    int hh = isQ ? nt : (nt - 16);
    int d0 = lane * 4;
    int sec = (d0 < 16) ? 0 : (d0 < 40) ? 1 : (d0 < 64) ? 2 : (d0 < 80) ? 0 : (d0 < 104) ? 1 : 2;
    #pragma unroll 1
    for (int rr = 0; rr < 16; rr++) {
        int row = warp * 16 + rr;
        int t = mt * 128 + row;
        int bb = t >> 10, s = t & 1023;
        size_t ci = (((size_t)sec * B_ + bb) * S_ + s) * HD_ + d0;
        float c4[4], s4[4];
        *(float4*)c4 = *(const float4*)(cosb + ci);
        *(float4*)s4 = *(const float4*)(sinb + ci);
        float outv[4];
        #pragma unroll
        for (int j = 0; j < 4; j++) {
            int d = d0 + j;
            float nv = snv[row * 128 + ((d + 4 * row) & 127)];
            float pn = snv[row * 128 + (((d ^ 64) + 4 * row) & 127)];
            float part = (d < 64) ? -pn : pn;
            outv[j] = nv * c4[j] + part * s4[j];
        }
        if (isQ) {
            unsigned short h[4], l[4];
            #pragma unroll
            for (int j = 0; j < 4; j++) split_h(outv[j], h[j], l[j]);
            __half* qp = Qpk + ((size_t)(bb * NH_ + hh) * S_ + s) * 256;
            *(uint2*)(qp + d0)       = make_uint2(pack2(h[0], h[1]), pack2(h[2], h[3]));
            *(uint2*)(qp + 128 + d0) = make_uint2(pack2(l[0], l[1]), pack2(l[2], l[3]));
        } else {
            float mval = mask[t];
            unsigned short h[4];
            #pragma unroll
            for (int j = 0; j < 4; j++) h[j] = __half_as_ushort(__float2half_rn(outv[j] * mval));
            __half* kp = Kpk + ((size_t)(bb * NKV_ + hh) * S_ + s) * 128;
            *(uint2*)(kp + d0) = make_uint2(pack2(h[0], h[1]), pack2(h[2], h[3]));
        }
    }
}

// ---------------- tensor-core flash attention (fp16), unchanged from R6 ----------------
#define ATTN_SMEM 98304

__global__ void __launch_bounds__(128, 2) attn_tc_kernel(
    const __half* __restrict__ Qpk, const __half* __restrict__ Kpk,
    const __half* __restrict__ Vpk, const float* __restrict__ eff,
    __half* __restrict__ Apk)
{
    extern __shared__ char smc[];
    uint32_t sbase = smem_u32(smc);

    int bid = blockIdx.x;
    int qt = 15 - (bid >> 5);
    int rem = bid & 31;
    int h = rem >> 1, b = rem & 1;
    int kvh = h / G_;
    int tid = threadIdx.x, warp = tid >> 5, lane = tid & 31;

    const __half* Qg = Qpk + ((size_t)(b * NH_ + h) * S_ + qt * 64) * 256;
    const __half* Kg = Kpk + ((size_t)(b * NKV_ + kvh) * S_) * 128;
    const __half* Vg = Vpk + ((size_t)(b * NKV_ + kvh) * S_) * 128;

    #pragma unroll
    for (int it = 0; it < 16; it++) {
        int idx = it * 128 + tid;
        int r = idx >> 5, c = idx & 31;
        cp_async16(sbase + r * 512 + csw(c, r) * 16, Qg + (size_t)r * 256 + c * 8);
    }
    cp_commit();
    cp_wait<0>();
    __syncthreads();

    uint32_t qh[8][4], ql[8][4];
    {
        int row = warp * 16 + ((lane >> 3) & 1) * 8 + (lane & 7);
        uint32_t roff = sbase + row * 512;
        uint32_t r7 = row & 7;
        int chi = (lane >> 4) & 1;
        #pragma unroll
        for (int j = 0; j < 8; j++) {
            uint32_t ch = 2 * j + chi;
            ldsm_x4(qh[j], roff + ((ch ^ r7) & 15u) * 16);
            ldsm_x4(ql[j], roff + (16u | ((ch ^ r7) & 15u)) * 16);
        }
    }

    int ntiles = qt + 1;
    int eff_i = (int)(eff[b] + 0.5f);

    #pragma unroll
    for (int pt = 0; pt < 2; pt++) {
        if (pt < ntiles) {
            #pragma unroll
            for (int it = 0; it < 8; it++) {
                int idx = it * 128 + tid;
                int r = idx >> 4, c = idx & 15;
                uint32_t ds = 32768u + (uint32_t)pt * 32768 + r * 256 + csw8(c, r) * 16;
                size_t go = (size_t)(pt * 64 + r) * 128 + c * 8;
                cp_async16(sbase + ds,         Kg + go);
                cp_async16(sbase + ds + 16384, Vg + go);
            }
        }
        cp_commit();
    }

    float m0 = -1e30f, m1 = -1e30f, ls0 = 0.f, ls1 = 0.f;
    float o[16][4];
    #pragma unroll
    for (int i = 0; i < 16; i++) { o[i][0] = o[i][1] = o[i][2] = o[i][3] = 0.f; }

    const float scale = 0.08838834764831845f;
    int row0 = qt * 64 + warp * 16 + (lane >> 2);
    int colb = (lane & 3) * 2;
    int krbase = ((lane >> 4) & 1) * 8 + (lane & 7);
    int kchi = (lane >> 3) & 1;
    int vrbase = ((lane >> 3) & 1) * 8 + (lane & 7);
    int vchi = (lane >> 4) & 1;

    for (int kt = 0; kt < ntiles; kt++) {
        cp_wait<1>();
        __syncthreads();
        uint32_t sk = sbase + 32768u + (uint32_t)(kt & 1) * 32768;
        uint32_t sv = sk + 16384;

        float s[8][4];
        #pragma unroll
        for (int i = 0; i < 8; i++) { s[i][0] = s[i][1] = s[i][2] = s[i][3] = 0.f; }

        #pragma unroll
        for (int nbp = 0; nbp < 4; nbp++) {
            int krow = nbp * 16 + krbase;
            uint32_t kroff = sk + krow * 256;
            uint32_t kr7 = krow & 7;
            #pragma unroll
            for (int j = 0; j < 8; j++) {
                uint32_t ch = 2 * j + kchi;
                uint32_t kf[4];
                ldsm_x4(kf, kroff + ((ch & 8u) | ((ch ^ kr7) & 7u)) * 16);
                mma_16816(s[2*nbp],   qh[j], kf[0], kf[1]);
                mma_16816(s[2*nbp+1], qh[j], kf[2], kf[3]);
                mma_16816(s[2*nbp],   ql[j], kf[0], kf[1]);
                mma_16816(s[2*nbp+1], ql[j], kf[2], kf[3]);
            }
        }

        float mx0 = -1e30f, mx1 = -1e30f;
        #pragma unroll
        for (int nb = 0; nb < 8; nb++) {
            int c0 = kt * 64 + nb * 8 + colb;
            #pragma unroll
            for (int e = 0; e < 2; e++) {
                int cc = c0 + e;
                float v0 = (cc <= row0     && cc < eff_i) ? s[nb][e]   * scale : -1e9f;
                float v1 = (cc <= row0 + 8 && cc < eff_i) ? s[nb][2+e] * scale : -1e9f;
                s[nb][e] = v0; s[nb][2+e] = v1;
                mx0 = fmaxf(mx0, v0); mx1 = fmaxf(mx1, v1);
            }
        }
        mx0 = fmaxf(mx0, __shfl_xor_sync(0xffffffffu, mx0, 1));
        mx0 = fmaxf(mx0, __shfl_xor_sync(0xffffffffu, mx0, 2));
        mx1 = fmaxf(mx1, __shfl_xor_sync(0xffffffffu, mx1, 1));
        mx1 = fmaxf(mx1, __shfl_xor_sync(0xffffffffu, mx1, 2));
        float m0n = fmaxf(m0, mx0), m1n = fmaxf(m1, mx1);
        float cr0 = __expf(m0 - m0n), cr1 = __expf(m1 - m1n);
        float sum0 = 0.f, sum1 = 0.f;
        #pragma unroll
        for (int nb = 0; nb < 8; nb++) {
            #pragma unroll
            for (int e = 0; e < 2; e++) {
                float p0 = __expf(s[nb][e]   - m0n);
                float p1 = __expf(s[nb][2+e] - m1n);
                s[nb][e] = p0; s[nb][2+e] = p1;
                sum0 += p0; sum1 += p1;
            }
        }
        sum0 += __shfl_xor_sync(0xffffffffu, sum0, 1);
        sum0 += __shfl_xor_sync(0xffffffffu, sum0, 2);
        sum1 += __shfl_xor_sync(0xffffffffu, sum1, 1);
        sum1 += __shfl_xor_sync(0xffffffffu, sum1, 2);
        ls0 = ls0 * cr0 + sum0; m0 = m0n;
        ls1 = ls1 * cr1 + sum1; m1 = m1n;
        #pragma unroll
        for (int i = 0; i < 16; i++) {
            o[i][0] *= cr0; o[i][1] *= cr0;
            o[i][2] *= cr1; o[i][3] *= cr1;
        }

        uint32_t ph[4][4], pl[4][4];
        #pragma unroll
        for (int j2 = 0; j2 < 4; j2++) {
            #pragma unroll
            for (int q = 0; q < 4; q++) {
                int nb = 2 * j2 + (q >> 1);
                int e  = (q & 1) * 2;
                unsigned short ha, la, hb, lb2;
                split_h(s[nb][e],     ha, la);
                split_h(s[nb][e + 1], hb, lb2);
                int slot = (q >> 1) * 2 + (q & 1);
                ph[j2][slot] = pack2(ha, hb);
                pl[j2][slot] = pack2(la, lb2);
            }
        }

        #pragma unroll
        for (int j2 = 0; j2 < 4; j2++) {
            int vrow = j2 * 16 + vrbase;
            uint32_t vroff = sv + vrow * 256;
            uint32_t vr7 = vrow & 7;
            #pragma unroll
            for (int nbp = 0; nbp < 8; nbp++) {
                uint32_t ch = 2 * nbp + vchi;
                uint32_t vf[4];
                ldsm_x4_t(vf, vroff + ((ch & 8u) | ((ch ^ vr7) & 7u)) * 16);
                mma_16816(o[2*nbp],   ph[j2], vf[0], vf[1]);
                mma_16816(o[2*nbp+1], ph[j2], vf[2], vf[3]);
                mma_16816(o[2*nbp],   pl[j2], vf[0], vf[1]);
                mma_16816(o[2*nbp+1], pl[j2], vf[2], vf[3]);
            }
        }

        __syncthreads();
        int nxt = kt + 2;
        if (nxt < ntiles) {
            #pragma unroll
            for (int it = 0; it < 8; it++) {
                int idx = it * 128 + tid;
                int r = idx >> 4, c = idx & 15;
                uint32_t ds = 32768u + (uint32_t)(kt & 1) * 32768 + r * 256 + csw8(c, r) * 16;
                size_t go = (size_t)(nxt * 64 + r) * 128 + c * 8;
                cp_async16(sbase + ds,         Kg + go);
                cp_async16(sbase + ds + 16384, Vg + go);
            }
        }
        cp_commit();
    }

    float inv0 = 1.0f / ls0, inv1 = 1.0f / ls1;
    int t0 = b * S_ + qt * 64 + warp * 16 + (lane >> 2);
    size_t r0b = (size_t)t0 * KPRIME;
    size_t r1b = (size_t)(t0 + 8) * KPRIME;
    #pragma unroll
    for (int db = 0; db < 16; db++) {
        int c = h * 128 + db * 8 + colb;
        unsigned short h0, l0, h1, l1;
        split_h(o[db][0] * inv0, h0, l0);
        split_h(o[db][1] * inv0, h1, l1);
        *(uint32_t*)(Apk + r0b + c)        = pack2(h0, h1);
        *(uint32_t*)(Apk + r0b + 2048 + c) = pack2(l0, l1);
        split_h(o[db][2] * inv1, h0, l0);
        split_h(o[db][3] * inv1, h1, l1);
        *(uint32_t*)(Apk + r1b + c)        = pack2(h0, h1);
        *(uint32_t*)(Apk + r1b + 2048 + c) = pack2(l0, l1);
    }
}

// ---------------- launcher ----------------
extern "C" void kernel_launch(void* const* d_in, const int* in_sizes, int n_in,
                              void* d_out, int out_size)
{
    const float* x       = (const float*)d_in[0];
    const float* cosb    = (const float*)d_in[1];
    const float* sinb    = (const float*)d_in[2];
    const float* mask    = (const float*)d_in[3];
    const float* q_w     = (const float*)d_in[4];
    const float* q_b     = (const float*)d_in[5];
    const float* k_w     = (const float*)d_in[6];
    const float* k_b     = (const float*)d_in[7];
    const float* v_w     = (const float*)d_in[8];
    const float* v_b     = (const float*)d_in[9];
    const float* q_gamma = (const float*)d_in[10];
    const float* k_gamma = (const float*)d_in[11];
    const float* o_w     = (const float*)d_in[12];
    float* out = (float*)d_out;

    float* scratch = nullptr;
    cudaGetSymbolAddress((void**)&scratch, g_scratch);
    float* geff = scratch + OFF_EFF;
    float* bias = scratch + OFF_BIAS;
    __half* Apack = (__half*)(scratch + OFF_APK);
    __half* Bqkv  = (__half*)(scratch + OFF_BQKV);
    __half* Bow   = (__half*)(scratch + OFF_BOW);
    __half* Qpk   = (__half*)(scratch + OFF_QPK);
    __half* Kpk   = (__half*)(scratch + OFF_KPK);
    __half* Vpk   = (__half*)(scratch + OFF_VPK);

    cudaFuncSetAttribute(gemm_mma_kernel, cudaFuncAttributeMaxDynamicSharedMemorySize, GEMM_SMEM);
    cudaFuncSetAttribute(gemm_qkv_fused,  cudaFuncAttributeMaxDynamicSharedMemorySize, GEMM_SMEM);
    cudaFuncSetAttribute(attn_tc_kernel,  cudaFuncAttributeMaxDynamicSharedMemorySize, ATTN_SMEM);

    eff_kernel<<<B_, 256>>>(mask, geff);
    biascat_kernel<<<10, 256>>>(q_b, k_b, v_b, bias);

    convA_kernel<<<2048, 256>>>(x, Apack);
    convB_kernel<<<dim3(64, 64), 256>>>(q_w, Bqkv, 2048, 0);
    convB_kernel<<<dim3(8, 64),  256>>>(k_w, Bqkv, 256, 2048);
    convB_kernel<<<dim3(8, 64),  256>>>(v_w, Bqkv, 256, 2304);
    convB_kernel<<<dim3(64, 64), 256>>>(o_w, Bow, 2048, 0);

    gemm_qkv_fused<<<dim3(NQKV / 128, 16), 256, GEMM_SMEM>>>(
        Apack, Bqkv, bias, cosb, sinb, mask, q_gamma, k_gamma, Qpk, Kpk, Vpk);

    attn_tc_kernel<<<512, 128, ATTN_SMEM>>>(Qpk, Kpk, Vpk, geff, Apack);

    gemm_mma_kernel<<<dim3(16, 16), 256, GEMM_SMEM>>>(Apack, Bow, out, 2048);
}